// round 3
// baseline (speedup 1.0000x reference)
#include <cuda_runtime.h>

#define NT 256

typedef unsigned long long u64;

// -------- persistent device scratch (no allocs allowed) --------
__device__ float g_h[65536 * 64];   // h = block2 output, needed for skip-concat
__device__ int   g_gmax[1024];      // global max-pool accumulator (float bits, >=0)
__device__ float g_c5[512];         // c5 = b5 + W5[:,64:] @ g

__device__ __forceinline__ float frelu(float v) { return v > 0.f ? v : 0.f; }

// ---- packed f32x2 helpers (FFMA2: 2x fp32 throughput on sm_103a) ----
__device__ __forceinline__ u64 fma2(u64 a, u64 b, u64 c) {
    u64 d; asm("fma.rn.f32x2 %0, %1, %2, %3;" : "=l"(d) : "l"(a), "l"(b), "l"(c)); return d;
}
__device__ __forceinline__ u64 splat2(float a) {
    u64 d; asm("mov.b64 %0, {%1, %1};" : "=l"(d) : "f"(a)); return d;
}
__device__ __forceinline__ u64 pack2(float lo, float hi) {
    u64 d; asm("mov.b64 %0, {%1, %2};" : "=l"(d) : "f"(lo), "f"(hi)); return d;
}
__device__ __forceinline__ float2 unpack2(u64 v) {
    float2 f; asm("mov.b64 {%0, %1}, %2;" : "=f"(f.x), "=f"(f.y) : "l"(v)); return f;
}

// ---- weight slab staging with register prefetch (16 floats/thread) ----
// Slab = [KS x CW] k-major in smem: Wb[k*(CW+4) + c]. KS*CW must equal 16*NT.
template <int KS, int CW>
__device__ __forceinline__ void ldgW16(float r[16], const float* __restrict__ W,
                                       int ldW, int cbase, int kbase) {
    static_assert(KS * CW == 16 * NT, "slab size");
#pragma unroll
    for (int j = 0; j < 16; j++) {
        int idx = threadIdx.x + j * NT;
        int c = idx / KS, k = idx % KS;
        r[j] = __ldg(W + (cbase + c) * ldW + (kbase + k));
    }
}
template <int KS, int CW>
__device__ __forceinline__ void stsW16(float* __restrict__ Wb, const float r[16]) {
#pragma unroll
    for (int j = 0; j < 16; j++) {
        int idx = threadIdx.x + j * NT;
        int c = idx / KS, k = idx % KS;
        Wb[k * (CW + 4) + c] = r[j];
    }
}

// ---- register-tiled GEMM slab with packed channel pairs ----
// Each thread: TP points x 8 channels (4 f32x2 accumulators per point).
// A: smem activations [p][k], row stride SA. Wb: smem k-major weights.
template <int TP, int PGR, int CW, int KS>
__device__ __forceinline__ void mma2(const float* __restrict__ A, int SA,
                                     const float* __restrict__ Wb,
                                     int pgrp, int cgrp, u64 acc[TP][4]) {
    constexpr int SWB = CW + 4;
    const float* Ap[TP];
#pragma unroll
    for (int i = 0; i < TP; i++) Ap[i] = A + (pgrp + i * PGR) * SA;
    const char* wbase = (const char*)(Wb + cgrp * 8);
#pragma unroll 8
    for (int k = 0; k < KS; k++) {
        ulonglong2 u0 = *(const ulonglong2*)(wbase + (size_t)k * (SWB * 4));
        ulonglong2 u1 = *(const ulonglong2*)(wbase + (size_t)k * (SWB * 4) + 16);
#pragma unroll
        for (int i = 0; i < TP; i++) {
            u64 a2 = splat2(Ap[i][k]);
            acc[i][0] = fma2(a2, u0.x, acc[i][0]);
            acc[i][1] = fma2(a2, u0.y, acc[i][1]);
            acc[i][2] = fma2(a2, u1.x, acc[i][2]);
            acc[i][3] = fma2(a2, u1.y, acc[i][3]);
        }
    }
}

// -------- init: reset max-pool accumulator each replay --------
__global__ void k_init() {
    g_gmax[threadIdx.x] = 0;  // relu outputs >= 0, so float bits 0 is identity
}

// ============================================================
// Kernel A: blocks 1..4 fused + per-CTA max + global atomicMax.
// CTA = 128 points, 256 threads.
// smem floats: a3[128*132] hbuf[128*68] Wb[64*68] gmax[1024] consts[1856]
// ============================================================
#define SMEM1_FLOATS (128 * 132 + 128 * 68 + 64 * 68 + 1024 + 1856)

__global__ __launch_bounds__(NT, 1) void k_front(
    const float* __restrict__ x,
    const float* __restrict__ W1, const float* __restrict__ b1,
    const float* __restrict__ W2, const float* __restrict__ b2,
    const float* __restrict__ W3, const float* __restrict__ b3,
    const float* __restrict__ W4, const float* __restrict__ b4) {
    extern __shared__ float sm[];
    float* a3   = sm;                      // [128][132]  (a1 first, then a3)
    float* hbuf = a3 + 128 * 132;          // [128][68]
    float* Wb   = hbuf + 128 * 68;         // [64][68]
    int*   gmax = (int*)(Wb + 64 * 68);    // [1024]
    float* cst  = (float*)(gmax + 1024);
    float* w1s = cst;          // 192
    float* b1s = cst + 192;    // 64
    float* xs  = cst + 256;    // 384
    float* b2s = cst + 640;    // 64
    float* b3s = cst + 704;    // 128
    float* b4s = cst + 832;    // 1024

    const int tid   = threadIdx.x;
    const int pbase = blockIdx.x * 128;

    for (int i = tid; i < 1024; i += NT) gmax[i] = 0;
    for (int i = tid; i < 192; i += NT) w1s[i] = W1[i];
    for (int i = tid; i < 64; i += NT) { b1s[i] = b1[i]; b2s[i] = b2[i]; }
    for (int i = tid; i < 128; i += NT) b3s[i] = b3[i];
    for (int i = tid; i < 1024; i += NT) b4s[i] = b4[i];
    for (int i = tid; i < 384; i += NT) xs[i] = x[pbase * 3 + i];

    float rw[16];
    ldgW16<64, 64>(rw, W2, 64, 0, 0);     // prefetch W2 slab
    __syncthreads();

    // ---- block1: a1 = relu(x @ W1^T + b1) -> a3[:, :64]
    for (int idx = tid; idx < 128 * 64; idx += NT) {
        int p = idx >> 6, c = idx & 63;
        float v = fmaf(xs[p * 3 + 2], w1s[c * 3 + 2],
                  fmaf(xs[p * 3 + 1], w1s[c * 3 + 1],
                  fmaf(xs[p * 3 + 0], w1s[c * 3 + 0], b1s[c])));
        a3[p * 132 + c] = frelu(v);
    }
    __syncthreads();

    stsW16<64, 64>(Wb, rw);
    ldgW16<64, 64>(rw, W3, 64, 0, 0);     // prefetch W3 chunk0
    __syncthreads();

    const int pgrp = tid >> 3;  // 0..31
    const int cgrp = tid & 7;   // 0..7
    const int c0   = cgrp * 8;

    // ---- block2: h = relu(a1 @ W2^T + b2) -> hbuf
    {
        u64 acc[4][4];
#pragma unroll
        for (int i = 0; i < 4; i++)
#pragma unroll
            for (int j = 0; j < 4; j++) acc[i][j] = pack2(b2s[c0 + 2 * j], b2s[c0 + 2 * j + 1]);
        mma2<4, 32, 64, 64>(a3, 132, Wb, pgrp, cgrp, acc);
#pragma unroll
        for (int i = 0; i < 4; i++)
#pragma unroll
            for (int j = 0; j < 4; j++) {
                float2 f = unpack2(acc[i][j]);
                hbuf[(pgrp + i * 32) * 68 + c0 + 2 * j]     = frelu(f.x);
                hbuf[(pgrp + i * 32) * 68 + c0 + 2 * j + 1] = frelu(f.y);
            }
    }
    __syncthreads();

    stsW16<64, 64>(Wb, rw);
    ldgW16<64, 64>(rw, W3, 64, 64, 0);    // prefetch W3 chunk1
    __syncthreads();

    // write h to global (needed by the back half)
    for (int idx = tid; idx < 128 * 64; idx += NT) {
        int p = idx >> 6, c = idx & 63;
        g_h[(pbase + p) * 64 + c] = hbuf[p * 68 + c];
    }

    // ---- block3 chunk 0: a3[:, :64]
    {
        u64 acc[4][4];
#pragma unroll
        for (int i = 0; i < 4; i++)
#pragma unroll
            for (int j = 0; j < 4; j++) acc[i][j] = pack2(b3s[c0 + 2 * j], b3s[c0 + 2 * j + 1]);
        mma2<4, 32, 64, 64>(hbuf, 68, Wb, pgrp, cgrp, acc);
#pragma unroll
        for (int i = 0; i < 4; i++)
#pragma unroll
            for (int j = 0; j < 4; j++) {
                float2 f = unpack2(acc[i][j]);
                a3[(pgrp + i * 32) * 132 + c0 + 2 * j]     = frelu(f.x);
                a3[(pgrp + i * 32) * 132 + c0 + 2 * j + 1] = frelu(f.y);
            }
    }
    __syncthreads();

    stsW16<64, 64>(Wb, rw);
    ldgW16<64, 64>(rw, W4, 128, 0, 0);    // prefetch W4 stage 0
    __syncthreads();

    // ---- block3 chunk 1: a3[:, 64:]
    {
        u64 acc[4][4];
#pragma unroll
        for (int i = 0; i < 4; i++)
#pragma unroll
            for (int j = 0; j < 4; j++) acc[i][j] = pack2(b3s[64 + c0 + 2 * j], b3s[64 + c0 + 2 * j + 1]);
        mma2<4, 32, 64, 64>(hbuf, 68, Wb, pgrp, cgrp, acc);
#pragma unroll
        for (int i = 0; i < 4; i++)
#pragma unroll
            for (int j = 0; j < 4; j++) {
                float2 f = unpack2(acc[i][j]);
                a3[(pgrp + i * 32) * 132 + 64 + c0 + 2 * j]     = frelu(f.x);
                a3[(pgrp + i * 32) * 132 + 64 + c0 + 2 * j + 1] = frelu(f.y);
            }
    }

    // ---- block4: 16 channel chunks x 2 k-substages (KS=64); only max kept
    for (int cc = 0; cc < 16; cc++) {
        u64 acc[4][4];
#pragma unroll
        for (int i = 0; i < 4; i++)
#pragma unroll
            for (int j = 0; j < 4; j++)
                acc[i][j] = pack2(b4s[cc * 64 + c0 + 2 * j], b4s[cc * 64 + c0 + 2 * j + 1]);
        for (int s = 0; s < 2; s++) {
            __syncthreads();
            stsW16<64, 64>(Wb, rw);
            int t = cc * 2 + s + 1;
            if (t < 32) ldgW16<64, 64>(rw, W4, 128, (t >> 1) * 64, (t & 1) * 64);
            __syncthreads();
            mma2<4, 32, 64, 64>(a3 + s * 64, 132, Wb, pgrp, cgrp, acc);
        }
#pragma unroll
        for (int j = 0; j < 4; j++) {
            float2 f0 = unpack2(acc[0][j]);
            float2 f1 = unpack2(acc[1][j]);
            float2 f2 = unpack2(acc[2][j]);
            float2 f3 = unpack2(acc[3][j]);
            float mx = frelu(fmaxf(fmaxf(f0.x, f1.x), fmaxf(f2.x, f3.x)));
            float my = frelu(fmaxf(fmaxf(f0.y, f1.y), fmaxf(f2.y, f3.y)));
            atomicMax(&gmax[cc * 64 + c0 + 2 * j],     __float_as_int(mx));
            atomicMax(&gmax[cc * 64 + c0 + 2 * j + 1], __float_as_int(my));
        }
    }
    __syncthreads();
    for (int i = tid; i < 1024; i += NT) atomicMax(&g_gmax[i], gmax[i]);
}

// ============================================================
// Kernel B: c5[j] = b5[j] + sum_i W5[j][64+i] * g[i]
// ============================================================
__global__ void k_c5(const float* __restrict__ W5, const float* __restrict__ b5) {
    __shared__ float gs[1024];
    const int tid = threadIdx.x;
    for (int i = tid; i < 1024; i += 256) gs[i] = __int_as_float(g_gmax[i]);
    __syncthreads();
    const int j = blockIdx.x * 64 + (tid >> 2);
    const int q = tid & 3;
    const float* wr = W5 + j * 1088 + 64 + q * 256;
    const float* gr = gs + q * 256;
    float s = 0.f;
#pragma unroll 8
    for (int i = 0; i < 256; i++) s = fmaf(wr[i], gr[i], s);
    s += __shfl_xor_sync(0xffffffffu, s, 1);
    s += __shfl_xor_sync(0xffffffffu, s, 2);
    if (q == 0) g_c5[j] = s + b5[j];
}

// ============================================================
// Kernel C: blocks 5..8 fused. CTA = 64 points, 256 threads.
// smem floats: z5[64*516] z6[64*260] Wb[32*132] consts[1056]
// (h overlays z6 region, z7 overlays z5 region)
// ============================================================
#define SMEM3_FLOATS (64 * 516 + 64 * 260 + 32 * 132 + 1056)

__global__ __launch_bounds__(NT, 1) void k_back(
    const float* __restrict__ W5,
    const float* __restrict__ W6, const float* __restrict__ b6,
    const float* __restrict__ W7, const float* __restrict__ b7,
    const float* __restrict__ W8, const float* __restrict__ b8,
    float* __restrict__ out) {
    extern __shared__ float sm[];
    float* z5  = sm;                    // [64][516]; z7 overlays as [64][132]
    float* z6  = z5 + 64 * 516;         // [64][260]; h overlays as [64][68]
    float* Wb  = z6 + 64 * 260;         // [32][132]
    float* cst = Wb + 32 * 132;
    float* c5s = cst;          // 512
    float* b6s = cst + 512;    // 256
    float* b7s = cst + 768;    // 128
    float* w8s = cst + 896;    // 128
    float* b8s = cst + 1024;   // 1
    float* hbuf = z6;          // stride 68 (h overlays z6 region during block5)

    const int tid   = threadIdx.x;
    const int pbase = blockIdx.x * 64;

    for (int i = tid; i < 512; i += NT) c5s[i] = g_c5[i];
    for (int i = tid; i < 256; i += NT) b6s[i] = b6[i];
    for (int i = tid; i < 128; i += NT) { b7s[i] = b7[i]; w8s[i] = W8[i]; }
    if (tid == 0) b8s[0] = b8[0];
    for (int idx = tid; idx < 64 * 64; idx += NT) {
        int p = idx >> 6, c = idx & 63;
        hbuf[p * 68 + c] = g_h[(pbase + p) * 64 + c];
    }

    float rw[16];
    ldgW16<32, 128>(rw, W5, 1088, 0, 0);   // prefetch W5 stage 0
    __syncthreads();

    const int pgrp = tid >> 4;  // 0..15
    const int cgrp = tid & 15;  // 0..15
    const int c0   = cgrp * 8;

    // ---- block5: z5 = relu(h @ W5a^T + c5), 4 chunks of 128 ch, K=64 (2 substages)
    for (int cc = 0; cc < 4; cc++) {
        u64 acc[4][4];
#pragma unroll
        for (int i = 0; i < 4; i++)
#pragma unroll
            for (int j = 0; j < 4; j++)
                acc[i][j] = pack2(c5s[cc * 128 + c0 + 2 * j], c5s[cc * 128 + c0 + 2 * j + 1]);
        for (int s = 0; s < 2; s++) {
            __syncthreads();
            stsW16<32, 128>(Wb, rw);
            int t = cc * 2 + s + 1;
            if (t < 8)       ldgW16<32, 128>(rw, W5, 1088, (t >> 1) * 128, (t & 1) * 32);
            else if (t == 8) ldgW16<32, 128>(rw, W6, 512, 0, 0);
            __syncthreads();
            mma2<4, 16, 128, 32>(hbuf + s * 32, 68, Wb, pgrp, cgrp, acc);
        }
#pragma unroll
        for (int i = 0; i < 4; i++)
#pragma unroll
            for (int j = 0; j < 4; j++) {
                float2 f = unpack2(acc[i][j]);
                z5[(pgrp + i * 16) * 516 + cc * 128 + c0 + 2 * j]     = frelu(f.x);
                z5[(pgrp + i * 16) * 516 + cc * 128 + c0 + 2 * j + 1] = frelu(f.y);
            }
    }

    // ---- block6: z6 = relu(z5 @ W6^T + b6), 2 chunks of 128 ch, K=512 (16 substages)
    for (int cc = 0; cc < 2; cc++) {
        u64 acc[4][4];
#pragma unroll
        for (int i = 0; i < 4; i++)
#pragma unroll
            for (int j = 0; j < 4; j++)
                acc[i][j] = pack2(b6s[cc * 128 + c0 + 2 * j], b6s[cc * 128 + c0 + 2 * j + 1]);
        for (int s = 0; s < 16; s++) {
            __syncthreads();
            stsW16<32, 128>(Wb, rw);
            int t = cc * 16 + s + 1;
            if (t < 32)       ldgW16<32, 128>(rw, W6, 512, (t >> 4) * 128, (t & 15) * 32);
            else if (t == 32) ldgW16<32, 128>(rw, W7, 256, 0, 0);
            __syncthreads();
            mma2<4, 16, 128, 32>(z5 + s * 32, 516, Wb, pgrp, cgrp, acc);
        }
#pragma unroll
        for (int i = 0; i < 4; i++)
#pragma unroll
            for (int j = 0; j < 4; j++) {
                float2 f = unpack2(acc[i][j]);
                z6[(pgrp + i * 16) * 260 + cc * 128 + c0 + 2 * j]     = frelu(f.x);
                z6[(pgrp + i * 16) * 260 + cc * 128 + c0 + 2 * j + 1] = frelu(f.y);
            }
    }

    // ---- block7: z7 = relu(z6 @ W7^T + b7), 128 ch, K=256 (8 substages)
    {
        u64 acc[4][4];
#pragma unroll
        for (int i = 0; i < 4; i++)
#pragma unroll
            for (int j = 0; j < 4; j++)
                acc[i][j] = pack2(b7s[c0 + 2 * j], b7s[c0 + 2 * j + 1]);
        for (int s = 0; s < 8; s++) {
            __syncthreads();
            stsW16<32, 128>(Wb, rw);
            if (s < 7) ldgW16<32, 128>(rw, W7, 256, 0, (s + 1) * 32);
            __syncthreads();
            mma2<4, 16, 128, 32>(z6 + s * 32, 260, Wb, pgrp, cgrp, acc);
        }
        float* z7 = z5;  // overlay (z5 dead after block6)
#pragma unroll
        for (int i = 0; i < 4; i++)
#pragma unroll
            for (int j = 0; j < 4; j++) {
                float2 f = unpack2(acc[i][j]);
                z7[(pgrp + i * 16) * 132 + c0 + 2 * j]     = frelu(f.x);
                z7[(pgrp + i * 16) * 132 + c0 + 2 * j + 1] = frelu(f.y);
            }
    }
    __syncthreads();

    // ---- block8: out = z7 @ W8^T + b8 (no relu)
    if (tid < 64) {
        const float* zr = z5 + tid * 132;
        float s = b8s[0];
#pragma unroll 8
        for (int k = 0; k < 128; k++) s = fmaf(zr[k], w8s[k], s);
        out[pbase + tid] = s;
    }
}

// ============================================================
extern "C" void kernel_launch(void* const* d_in, const int* in_sizes, int n_in,
                              void* d_out, int out_size) {
    const float* x  = (const float*)d_in[0];
    const float* W1 = (const float*)d_in[1];  const float* b1 = (const float*)d_in[2];
    const float* W2 = (const float*)d_in[3];  const float* b2 = (const float*)d_in[4];
    const float* W3 = (const float*)d_in[5];  const float* b3 = (const float*)d_in[6];
    const float* W4 = (const float*)d_in[7];  const float* b4 = (const float*)d_in[8];
    const float* W5 = (const float*)d_in[9];  const float* b5 = (const float*)d_in[10];
    const float* W6 = (const float*)d_in[11]; const float* b6 = (const float*)d_in[12];
    const float* W7 = (const float*)d_in[13]; const float* b7 = (const float*)d_in[14];
    const float* W8 = (const float*)d_in[15]; const float* b8 = (const float*)d_in[16];
    float* out = (float*)d_out;

    const int n = in_sizes[0] / 3;  // 65536

    const int smem1 = SMEM1_FLOATS * (int)sizeof(float);
    const int smem3 = SMEM3_FLOATS * (int)sizeof(float);
    cudaFuncSetAttribute(k_front, cudaFuncAttributeMaxDynamicSharedMemorySize, smem1);
    cudaFuncSetAttribute(k_back,  cudaFuncAttributeMaxDynamicSharedMemorySize, smem3);

    k_init<<<1, 1024>>>();
    k_front<<<n / 128, NT, smem1>>>(x, W1, b1, W2, b2, W3, b3, W4, b4);
    k_c5<<<8, 256>>>(W5, b5);
    k_back<<<n / 64, NT, smem3>>>(W5, W6, b6, W7, b7, W8, b8, out);
}

// round 4
// speedup vs baseline: 1.0005x; 1.0005x over previous
#include <cuda_runtime.h>

#define NT 256

typedef unsigned long long u64;

// -------- persistent device scratch (no allocs allowed) --------
__device__ float g_h[65536 * 64];   // h = block2 output, needed for skip-concat
__device__ int   g_gmax[1024];      // global max-pool accumulator (float bits, >=0)
__device__ float g_c5[512];         // c5 = b5 + W5[:,64:] @ g

__device__ __forceinline__ float frelu(float v) { return v > 0.f ? v : 0.f; }

// ---- packed f32x2 helpers (FFMA2: 2x fp32 throughput on sm_103a) ----
__device__ __forceinline__ u64 fma2(u64 a, u64 b, u64 c) {
    u64 d; asm("fma.rn.f32x2 %0, %1, %2, %3;" : "=l"(d) : "l"(a), "l"(b), "l"(c)); return d;
}
__device__ __forceinline__ u64 splat2(float a) {
    u64 d; asm("mov.b64 %0, {%1, %1};" : "=l"(d) : "f"(a)); return d;
}
__device__ __forceinline__ u64 pack2(float lo, float hi) {
    u64 d; asm("mov.b64 %0, {%1, %2};" : "=l"(d) : "f"(lo), "f"(hi)); return d;
}
__device__ __forceinline__ float2 unpack2(u64 v) {
    float2 f; asm("mov.b64 {%0, %1}, %2;" : "=f"(f.x), "=f"(f.y) : "l"(v)); return f;
}

// ---- weight slab staging with register prefetch (16 floats/thread) ----
// Slab = [KS x CW] k-major in smem: Wb[k*(CW+4) + c]. KS*CW must equal 16*NT.
template <int KS, int CW>
__device__ __forceinline__ void ldgW16(float r[16], const float* __restrict__ W,
                                       int ldW, int cbase, int kbase) {
    static_assert(KS * CW == 16 * NT, "slab size");
#pragma unroll
    for (int j = 0; j < 16; j++) {
        int idx = threadIdx.x + j * NT;
        int c = idx / KS, k = idx % KS;
        r[j] = __ldg(W + (cbase + c) * ldW + (kbase + k));
    }
}
template <int KS, int CW>
__device__ __forceinline__ void stsW16(float* __restrict__ Wb, const float r[16]) {
#pragma unroll
    for (int j = 0; j < 16; j++) {
        int idx = threadIdx.x + j * NT;
        int c = idx / KS, k = idx % KS;
        Wb[k * (CW + 4) + c] = r[j];
    }
}

// ---- register-tiled GEMM slab with packed channel pairs ----
// Each thread: TP points x 8 channels (4 f32x2 accumulators per point).
// A: smem activations [p][k], row stride SA. Wb: smem k-major weights.
template <int TP, int PGR, int CW, int KS>
__device__ __forceinline__ void mma2(const float* __restrict__ A, int SA,
                                     const float* __restrict__ Wb,
                                     int pgrp, int cgrp, u64 acc[TP][4]) {
    constexpr int SWB = CW + 4;
    const float* Ap[TP];
#pragma unroll
    for (int i = 0; i < TP; i++) Ap[i] = A + (pgrp + i * PGR) * SA;
    const char* wbase = (const char*)(Wb + cgrp * 8);
#pragma unroll 8
    for (int k = 0; k < KS; k++) {
        ulonglong2 u0 = *(const ulonglong2*)(wbase + (size_t)k * (SWB * 4));
        ulonglong2 u1 = *(const ulonglong2*)(wbase + (size_t)k * (SWB * 4) + 16);
#pragma unroll
        for (int i = 0; i < TP; i++) {
            u64 a2 = splat2(Ap[i][k]);
            acc[i][0] = fma2(a2, u0.x, acc[i][0]);
            acc[i][1] = fma2(a2, u0.y, acc[i][1]);
            acc[i][2] = fma2(a2, u1.x, acc[i][2]);
            acc[i][3] = fma2(a2, u1.y, acc[i][3]);
        }
    }
}

// -------- init: reset max-pool accumulator each replay --------
__global__ void k_init() {
    g_gmax[threadIdx.x] = 0;  // relu outputs >= 0, so float bits 0 is identity
}

// ============================================================
// Kernel A: blocks 1..4 fused + per-CTA max + global atomicMax.
// CTA = 128 points, 256 threads.
// smem floats: a3[128*132] hbuf[128*68] Wb[64*68] gmax[1024] consts[1856]
// ============================================================
#define SMEM1_FLOATS (128 * 132 + 128 * 68 + 64 * 68 + 1024 + 1856)

__global__ __launch_bounds__(NT, 1) void k_front(
    const float* __restrict__ x,
    const float* __restrict__ W1, const float* __restrict__ b1,
    const float* __restrict__ W2, const float* __restrict__ b2,
    const float* __restrict__ W3, const float* __restrict__ b3,
    const float* __restrict__ W4, const float* __restrict__ b4) {
    extern __shared__ float sm[];
    float* a3   = sm;                      // [128][132]  (a1 first, then a3)
    float* hbuf = a3 + 128 * 132;          // [128][68]
    float* Wb   = hbuf + 128 * 68;         // [64][68]
    int*   gmax = (int*)(Wb + 64 * 68);    // [1024]
    float* cst  = (float*)(gmax + 1024);
    float* w1s = cst;          // 192
    float* b1s = cst + 192;    // 64
    float* xs  = cst + 256;    // 384
    float* b2s = cst + 640;    // 64
    float* b3s = cst + 704;    // 128
    float* b4s = cst + 832;    // 1024

    const int tid   = threadIdx.x;
    const int pbase = blockIdx.x * 128;

    for (int i = tid; i < 1024; i += NT) gmax[i] = 0;
    for (int i = tid; i < 192; i += NT) w1s[i] = W1[i];
    for (int i = tid; i < 64; i += NT) { b1s[i] = b1[i]; b2s[i] = b2[i]; }
    for (int i = tid; i < 128; i += NT) b3s[i] = b3[i];
    for (int i = tid; i < 1024; i += NT) b4s[i] = b4[i];
    for (int i = tid; i < 384; i += NT) xs[i] = x[pbase * 3 + i];

    float rw[16];
    ldgW16<64, 64>(rw, W2, 64, 0, 0);     // prefetch W2 slab
    __syncthreads();

    // ---- block1: a1 = relu(x @ W1^T + b1) -> a3[:, :64]
    for (int idx = tid; idx < 128 * 64; idx += NT) {
        int p = idx >> 6, c = idx & 63;
        float v = fmaf(xs[p * 3 + 2], w1s[c * 3 + 2],
                  fmaf(xs[p * 3 + 1], w1s[c * 3 + 1],
                  fmaf(xs[p * 3 + 0], w1s[c * 3 + 0], b1s[c])));
        a3[p * 132 + c] = frelu(v);
    }
    __syncthreads();

    stsW16<64, 64>(Wb, rw);
    ldgW16<64, 64>(rw, W3, 64, 0, 0);     // prefetch W3 chunk0
    __syncthreads();

    const int pgrp = tid >> 3;  // 0..31
    const int cgrp = tid & 7;   // 0..7
    const int c0   = cgrp * 8;

    // ---- block2: h = relu(a1 @ W2^T + b2) -> hbuf
    {
        u64 acc[4][4];
#pragma unroll
        for (int i = 0; i < 4; i++)
#pragma unroll
            for (int j = 0; j < 4; j++) acc[i][j] = pack2(b2s[c0 + 2 * j], b2s[c0 + 2 * j + 1]);
        mma2<4, 32, 64, 64>(a3, 132, Wb, pgrp, cgrp, acc);
#pragma unroll
        for (int i = 0; i < 4; i++)
#pragma unroll
            for (int j = 0; j < 4; j++) {
                float2 f = unpack2(acc[i][j]);
                hbuf[(pgrp + i * 32) * 68 + c0 + 2 * j]     = frelu(f.x);
                hbuf[(pgrp + i * 32) * 68 + c0 + 2 * j + 1] = frelu(f.y);
            }
    }
    __syncthreads();

    stsW16<64, 64>(Wb, rw);
    ldgW16<64, 64>(rw, W3, 64, 64, 0);    // prefetch W3 chunk1
    __syncthreads();

    // write h to global (needed by the back half)
    for (int idx = tid; idx < 128 * 64; idx += NT) {
        int p = idx >> 6, c = idx & 63;
        g_h[(pbase + p) * 64 + c] = hbuf[p * 68 + c];
    }

    // ---- block3 chunk 0: a3[:, :64]
    {
        u64 acc[4][4];
#pragma unroll
        for (int i = 0; i < 4; i++)
#pragma unroll
            for (int j = 0; j < 4; j++) acc[i][j] = pack2(b3s[c0 + 2 * j], b3s[c0 + 2 * j + 1]);
        mma2<4, 32, 64, 64>(hbuf, 68, Wb, pgrp, cgrp, acc);
#pragma unroll
        for (int i = 0; i < 4; i++)
#pragma unroll
            for (int j = 0; j < 4; j++) {
                float2 f = unpack2(acc[i][j]);
                a3[(pgrp + i * 32) * 132 + c0 + 2 * j]     = frelu(f.x);
                a3[(pgrp + i * 32) * 132 + c0 + 2 * j + 1] = frelu(f.y);
            }
    }
    __syncthreads();

    stsW16<64, 64>(Wb, rw);
    ldgW16<64, 64>(rw, W4, 128, 0, 0);    // prefetch W4 stage 0
    __syncthreads();

    // ---- block3 chunk 1: a3[:, 64:]
    {
        u64 acc[4][4];
#pragma unroll
        for (int i = 0; i < 4; i++)
#pragma unroll
            for (int j = 0; j < 4; j++) acc[i][j] = pack2(b3s[64 + c0 + 2 * j], b3s[64 + c0 + 2 * j + 1]);
        mma2<4, 32, 64, 64>(hbuf, 68, Wb, pgrp, cgrp, acc);
#pragma unroll
        for (int i = 0; i < 4; i++)
#pragma unroll
            for (int j = 0; j < 4; j++) {
                float2 f = unpack2(acc[i][j]);
                a3[(pgrp + i * 32) * 132 + 64 + c0 + 2 * j]     = frelu(f.x);
                a3[(pgrp + i * 32) * 132 + 64 + c0 + 2 * j + 1] = frelu(f.y);
            }
    }

    // ---- block4: 16 channel chunks x 2 k-substages (KS=64); only max kept
    for (int cc = 0; cc < 16; cc++) {
        u64 acc[4][4];
#pragma unroll
        for (int i = 0; i < 4; i++)
#pragma unroll
            for (int j = 0; j < 4; j++)
                acc[i][j] = pack2(b4s[cc * 64 + c0 + 2 * j], b4s[cc * 64 + c0 + 2 * j + 1]);
        for (int s = 0; s < 2; s++) {
            __syncthreads();
            stsW16<64, 64>(Wb, rw);
            int t = cc * 2 + s + 1;
            if (t < 32) ldgW16<64, 64>(rw, W4, 128, (t >> 1) * 64, (t & 1) * 64);
            __syncthreads();
            mma2<4, 32, 64, 64>(a3 + s * 64, 132, Wb, pgrp, cgrp, acc);
        }
#pragma unroll
        for (int j = 0; j < 4; j++) {
            float2 f0 = unpack2(acc[0][j]);
            float2 f1 = unpack2(acc[1][j]);
            float2 f2 = unpack2(acc[2][j]);
            float2 f3 = unpack2(acc[3][j]);
            float mx = frelu(fmaxf(fmaxf(f0.x, f1.x), fmaxf(f2.x, f3.x)));
            float my = frelu(fmaxf(fmaxf(f0.y, f1.y), fmaxf(f2.y, f3.y)));
            atomicMax(&gmax[cc * 64 + c0 + 2 * j],     __float_as_int(mx));
            atomicMax(&gmax[cc * 64 + c0 + 2 * j + 1], __float_as_int(my));
        }
    }
    __syncthreads();
    for (int i = tid; i < 1024; i += NT) atomicMax(&g_gmax[i], gmax[i]);
}

// ============================================================
// Kernel B: c5[j] = b5[j] + sum_i W5[j][64+i] * g[i]
// ============================================================
__global__ void k_c5(const float* __restrict__ W5, const float* __restrict__ b5) {
    __shared__ float gs[1024];
    const int tid = threadIdx.x;
    for (int i = tid; i < 1024; i += 256) gs[i] = __int_as_float(g_gmax[i]);
    __syncthreads();
    const int j = blockIdx.x * 64 + (tid >> 2);
    const int q = tid & 3;
    const float* wr = W5 + j * 1088 + 64 + q * 256;
    const float* gr = gs + q * 256;
    float s = 0.f;
#pragma unroll 8
    for (int i = 0; i < 256; i++) s = fmaf(wr[i], gr[i], s);
    s += __shfl_xor_sync(0xffffffffu, s, 1);
    s += __shfl_xor_sync(0xffffffffu, s, 2);
    if (q == 0) g_c5[j] = s + b5[j];
}

// ============================================================
// Kernel C: blocks 5..8 fused. CTA = 64 points, 256 threads.
// smem floats: z5[64*516] z6[64*260] Wb[32*132] consts[1056]
// (h overlays z6 region, z7 overlays z5 region)
// ============================================================
#define SMEM3_FLOATS (64 * 516 + 64 * 260 + 32 * 132 + 1056)

__global__ __launch_bounds__(NT, 1) void k_back(
    const float* __restrict__ W5,
    const float* __restrict__ W6, const float* __restrict__ b6,
    const float* __restrict__ W7, const float* __restrict__ b7,
    const float* __restrict__ W8, const float* __restrict__ b8,
    float* __restrict__ out) {
    extern __shared__ float sm[];
    float* z5  = sm;                    // [64][516]; z7 overlays as [64][132]
    float* z6  = z5 + 64 * 516;         // [64][260]; h overlays as [64][68]
    float* Wb  = z6 + 64 * 260;         // [32][132]
    float* cst = Wb + 32 * 132;
    float* c5s = cst;          // 512
    float* b6s = cst + 512;    // 256
    float* b7s = cst + 768;    // 128
    float* w8s = cst + 896;    // 128
    float* b8s = cst + 1024;   // 1
    float* hbuf = z6;          // stride 68 (h overlays z6 region during block5)

    const int tid   = threadIdx.x;
    const int pbase = blockIdx.x * 64;

    for (int i = tid; i < 512; i += NT) c5s[i] = g_c5[i];
    for (int i = tid; i < 256; i += NT) b6s[i] = b6[i];
    for (int i = tid; i < 128; i += NT) { b7s[i] = b7[i]; w8s[i] = W8[i]; }
    if (tid == 0) b8s[0] = b8[0];
    for (int idx = tid; idx < 64 * 64; idx += NT) {
        int p = idx >> 6, c = idx & 63;
        hbuf[p * 68 + c] = g_h[(pbase + p) * 64 + c];
    }

    float rw[16];
    ldgW16<32, 128>(rw, W5, 1088, 0, 0);   // prefetch W5 stage 0
    __syncthreads();

    const int pgrp = tid >> 4;  // 0..15
    const int cgrp = tid & 15;  // 0..15
    const int c0   = cgrp * 8;

    // ---- block5: z5 = relu(h @ W5a^T + c5), 4 chunks of 128 ch, K=64 (2 substages)
    for (int cc = 0; cc < 4; cc++) {
        u64 acc[4][4];
#pragma unroll
        for (int i = 0; i < 4; i++)
#pragma unroll
            for (int j = 0; j < 4; j++)
                acc[i][j] = pack2(c5s[cc * 128 + c0 + 2 * j], c5s[cc * 128 + c0 + 2 * j + 1]);
        for (int s = 0; s < 2; s++) {
            __syncthreads();
            stsW16<32, 128>(Wb, rw);
            int t = cc * 2 + s + 1;
            if (t < 8)       ldgW16<32, 128>(rw, W5, 1088, (t >> 1) * 128, (t & 1) * 32);
            else if (t == 8) ldgW16<32, 128>(rw, W6, 512, 0, 0);
            __syncthreads();
            mma2<4, 16, 128, 32>(hbuf + s * 32, 68, Wb, pgrp, cgrp, acc);
        }
#pragma unroll
        for (int i = 0; i < 4; i++)
#pragma unroll
            for (int j = 0; j < 4; j++) {
                float2 f = unpack2(acc[i][j]);
                z5[(pgrp + i * 16) * 516 + cc * 128 + c0 + 2 * j]     = frelu(f.x);
                z5[(pgrp + i * 16) * 516 + cc * 128 + c0 + 2 * j + 1] = frelu(f.y);
            }
    }

    // ---- block6: z6 = relu(z5 @ W6^T + b6), 2 chunks of 128 ch, K=512 (16 substages)
    for (int cc = 0; cc < 2; cc++) {
        u64 acc[4][4];
#pragma unroll
        for (int i = 0; i < 4; i++)
#pragma unroll
            for (int j = 0; j < 4; j++)
                acc[i][j] = pack2(b6s[cc * 128 + c0 + 2 * j], b6s[cc * 128 + c0 + 2 * j + 1]);
        for (int s = 0; s < 16; s++) {
            __syncthreads();
            stsW16<32, 128>(Wb, rw);
            int t = cc * 16 + s + 1;
            if (t < 32)       ldgW16<32, 128>(rw, W6, 512, (t >> 4) * 128, (t & 15) * 32);
            else if (t == 32) ldgW16<32, 128>(rw, W7, 256, 0, 0);
            __syncthreads();
            mma2<4, 16, 128, 32>(z5 + s * 32, 516, Wb, pgrp, cgrp, acc);
        }
#pragma unroll
        for (int i = 0; i < 4; i++)
#pragma unroll
            for (int j = 0; j < 4; j++) {
                float2 f = unpack2(acc[i][j]);
                z6[(pgrp + i * 16) * 260 + cc * 128 + c0 + 2 * j]     = frelu(f.x);
                z6[(pgrp + i * 16) * 260 + cc * 128 + c0 + 2 * j + 1] = frelu(f.y);
            }
    }

    // ---- block7: z7 = relu(z6 @ W7^T + b7), 128 ch, K=256 (8 substages)
    {
        u64 acc[4][4];
#pragma unroll
        for (int i = 0; i < 4; i++)
#pragma unroll
            for (int j = 0; j < 4; j++)
                acc[i][j] = pack2(b7s[c0 + 2 * j], b7s[c0 + 2 * j + 1]);
        for (int s = 0; s < 8; s++) {
            __syncthreads();
            stsW16<32, 128>(Wb, rw);
            if (s < 7) ldgW16<32, 128>(rw, W7, 256, 0, (s + 1) * 32);
            __syncthreads();
            mma2<4, 16, 128, 32>(z6 + s * 32, 260, Wb, pgrp, cgrp, acc);
        }
        float* z7 = z5;  // overlay (z5 dead after block6)
#pragma unroll
        for (int i = 0; i < 4; i++)
#pragma unroll
            for (int j = 0; j < 4; j++) {
                float2 f = unpack2(acc[i][j]);
                z7[(pgrp + i * 16) * 132 + c0 + 2 * j]     = frelu(f.x);
                z7[(pgrp + i * 16) * 132 + c0 + 2 * j + 1] = frelu(f.y);
            }
    }
    __syncthreads();

    // ---- block8: out = z7 @ W8^T + b8 (no relu)
    if (tid < 64) {
        const float* zr = z5 + tid * 132;
        float s = b8s[0];
#pragma unroll 8
        for (int k = 0; k < 128; k++) s = fmaf(zr[k], w8s[k], s);
        out[pbase + tid] = s;
    }
}

// ============================================================
extern "C" void kernel_launch(void* const* d_in, const int* in_sizes, int n_in,
                              void* d_out, int out_size) {
    const float* x  = (const float*)d_in[0];
    const float* W1 = (const float*)d_in[1];  const float* b1 = (const float*)d_in[2];
    const float* W2 = (const float*)d_in[3];  const float* b2 = (const float*)d_in[4];
    const float* W3 = (const float*)d_in[5];  const float* b3 = (const float*)d_in[6];
    const float* W4 = (const float*)d_in[7];  const float* b4 = (const float*)d_in[8];
    const float* W5 = (const float*)d_in[9];  const float* b5 = (const float*)d_in[10];
    const float* W6 = (const float*)d_in[11]; const float* b6 = (const float*)d_in[12];
    const float* W7 = (const float*)d_in[13]; const float* b7 = (const float*)d_in[14];
    const float* W8 = (const float*)d_in[15]; const float* b8 = (const float*)d_in[16];
    float* out = (float*)d_out;

    const int n = in_sizes[0] / 3;  // 65536

    const int smem1 = SMEM1_FLOATS * (int)sizeof(float);
    const int smem3 = SMEM3_FLOATS * (int)sizeof(float);
    cudaFuncSetAttribute(k_front, cudaFuncAttributeMaxDynamicSharedMemorySize, smem1);
    cudaFuncSetAttribute(k_back,  cudaFuncAttributeMaxDynamicSharedMemorySize, smem3);

    k_init<<<1, 1024>>>();
    k_front<<<n / 128, NT, smem1>>>(x, W1, b1, W2, b2, W3, b3, W4, b4);
    k_c5<<<8, 256>>>(W5, b5);
    k_back<<<n / 64, NT, smem3>>>(W5, W6, b6, W7, b7, W8, b8, out);
}

// round 5
// speedup vs baseline: 1.4868x; 1.4862x over previous
#include <cuda_runtime.h>

#define NT 256

typedef unsigned long long u64;

// -------- persistent device scratch (no allocs allowed) --------
__device__ float g_h[65536 * 64];   // h = block2 output, needed for skip-concat
__device__ int   g_gmax[1024];      // global max-pool accumulator (float bits, >=0)
__device__ float g_c5[512];         // c5 = b5 + W5[:,64:] @ g

__device__ __forceinline__ float frelu(float v) { return v > 0.f ? v : 0.f; }

// ---- packed f32x2 helpers (FFMA2: 2x fp32 throughput on sm_103a) ----
__device__ __forceinline__ u64 fma2(u64 a, u64 b, u64 c) {
    u64 d; asm("fma.rn.f32x2 %0, %1, %2, %3;" : "=l"(d) : "l"(a), "l"(b), "l"(c)); return d;
}
__device__ __forceinline__ u64 splat2(float a) {
    u64 d; asm("mov.b64 %0, {%1, %1};" : "=l"(d) : "f"(a)); return d;
}
__device__ __forceinline__ u64 pack2(float lo, float hi) {
    u64 d; asm("mov.b64 %0, {%1, %2};" : "=l"(d) : "f"(lo), "f"(hi)); return d;
}
__device__ __forceinline__ float2 unpack2(u64 v) {
    float2 f; asm("mov.b64 {%0, %1}, %2;" : "=f"(f.x), "=f"(f.y) : "l"(v)); return f;
}

// ============================================================
// Weight slab staging (k-major, stride CW+4), 16 floats/thread,
// register prefetch. Global reads are k-fast (coalesced).
// ============================================================
template <int KS, int CW>
__device__ __forceinline__ void ldgWn(float rw[16], const float* __restrict__ W,
                                      int ldW, int cbase, int kbase) {
    static_assert(KS * CW == 16 * NT, "slab size");
#pragma unroll
    for (int j = 0; j < 16; j++) {
        int idx = threadIdx.x + j * NT;
        int c = idx / KS, k = idx % KS;
        rw[j] = __ldg(W + (cbase + c) * ldW + kbase + k);
    }
}
template <int KS, int CW>
__device__ __forceinline__ void stsWn(float* __restrict__ Wb, const float rw[16]) {
#pragma unroll
    for (int j = 0; j < 16; j++) {
        int idx = threadIdx.x + j * NT;
        int c = idx / KS, k = idx % KS;
        Wb[k * (CW + 4) + c] = rw[j];
    }
}

// ============================================================
// Wide register-tiled MMA: TP points x TC channels per thread.
// A: smem acts [p][k] row stride SA (broadcast reads).
// Wb: smem k-major weights, row stride CWP floats.
// ============================================================
template <int TP, int PGR, int TC, int KS>
__device__ __forceinline__ void mmaW(const float* __restrict__ A, int SA,
                                     const float* __restrict__ Wb, int CWP,
                                     int pgrp, int cgrp, u64 acc[TP][TC / 2]) {
    const float* Ap[TP];
#pragma unroll
    for (int i = 0; i < TP; i++) Ap[i] = A + (pgrp + i * PGR) * SA;
    const char* wp = (const char*)(Wb + cgrp * TC);
#pragma unroll 8
    for (int k = 0; k < KS; k++) {
        ulonglong2 u0 = *(const ulonglong2*)(wp + (size_t)k * (CWP * 4));
        ulonglong2 u1;
        if (TC == 8) u1 = *(const ulonglong2*)(wp + (size_t)k * (CWP * 4) + 16);
#pragma unroll
        for (int i = 0; i < TP; i++) {
            u64 a2 = splat2(Ap[i][k]);
            acc[i][0] = fma2(a2, u0.x, acc[i][0]);
            acc[i][1] = fma2(a2, u0.y, acc[i][1]);
            if (TC == 8) {
                acc[i][2] = fma2(a2, u1.x, acc[i][2]);
                acc[i][3] = fma2(a2, u1.y, acc[i][3]);
            }
        }
    }
}

// ---- small-tile path (blocks 2-3 only; old layout SWB=CW+4) ----
template <int KS, int CW>
__device__ __forceinline__ void ldgW16(float r[16], const float* __restrict__ W,
                                       int ldW, int cbase, int kbase) {
#pragma unroll
    for (int j = 0; j < 16; j++) {
        int idx = threadIdx.x + j * NT;
        int c = idx / KS, k = idx % KS;
        r[j] = __ldg(W + (cbase + c) * ldW + (kbase + k));
    }
}
template <int KS, int CW>
__device__ __forceinline__ void stsW16(float* __restrict__ Wb, const float r[16]) {
#pragma unroll
    for (int j = 0; j < 16; j++) {
        int idx = threadIdx.x + j * NT;
        int c = idx / KS, k = idx % KS;
        Wb[k * (CW + 4) + c] = r[j];
    }
}
template <int TP, int PGR, int CW, int KS>
__device__ __forceinline__ void mma2(const float* __restrict__ A, int SA,
                                     const float* __restrict__ Wb,
                                     int pgrp, int cgrp, u64 acc[TP][4]) {
    constexpr int SWB = CW + 4;
    const float* Ap[TP];
#pragma unroll
    for (int i = 0; i < TP; i++) Ap[i] = A + (pgrp + i * PGR) * SA;
    const char* wbase = (const char*)(Wb + cgrp * 8);
#pragma unroll 8
    for (int k = 0; k < KS; k++) {
        ulonglong2 u0 = *(const ulonglong2*)(wbase + (size_t)k * (SWB * 4));
        ulonglong2 u1 = *(const ulonglong2*)(wbase + (size_t)k * (SWB * 4) + 16);
#pragma unroll
        for (int i = 0; i < TP; i++) {
            u64 a2 = splat2(Ap[i][k]);
            acc[i][0] = fma2(a2, u0.x, acc[i][0]);
            acc[i][1] = fma2(a2, u0.y, acc[i][1]);
            acc[i][2] = fma2(a2, u1.x, acc[i][2]);
            acc[i][3] = fma2(a2, u1.y, acc[i][3]);
        }
    }
}

// -------- init: reset max-pool accumulator each replay --------
__global__ void k_init() {
    g_gmax[threadIdx.x] = 0;  // relu outputs >= 0, so float bits 0 is identity
}

// ============================================================
// Kernel A: blocks 1..4 fused + per-CTA max + global atomicMax.
// CTA = 128 points, 256 threads.
// ============================================================
#define SMEM1_FLOATS (128 * 130 + 128 * 68 + 4352 + 1024 + 832)

__global__ __launch_bounds__(NT, 1) void k_front(
    const float* __restrict__ x,
    const float* __restrict__ W1, const float* __restrict__ b1,
    const float* __restrict__ W2, const float* __restrict__ b2,
    const float* __restrict__ W3, const float* __restrict__ b3,
    const float* __restrict__ W4, const float* __restrict__ b4) {
    extern __shared__ float sm[];
    float* a3   = sm;                      // [128][130]
    float* hbuf = a3 + 128 * 130;          // [128][68]
    float* Wb   = hbuf + 128 * 68;         // 4352 floats (both slab shapes fit)
    int*   gmax = (int*)(Wb + 4352);       // [1024]
    float* cst  = (float*)(gmax + 1024);
    float* w1s = cst;          // 192
    float* b1s = cst + 192;    // 64
    float* xs  = cst + 256;    // 384
    float* b2s = cst + 640;    // 64
    float* b3s = cst + 704;    // 128

    const int tid   = threadIdx.x;
    const int pbase = blockIdx.x * 128;

    for (int i = tid; i < 1024; i += NT) gmax[i] = 0;
    for (int i = tid; i < 192; i += NT) w1s[i] = W1[i];
    for (int i = tid; i < 64; i += NT) { b1s[i] = b1[i]; b2s[i] = b2[i]; }
    for (int i = tid; i < 128; i += NT) b3s[i] = b3[i];
    for (int i = tid; i < 384; i += NT) xs[i] = x[pbase * 3 + i];

    float rw[16];
    ldgW16<64, 64>(rw, W2, 64, 0, 0);     // prefetch W2 slab
    __syncthreads();

    // ---- block1: a1 = relu(x @ W1^T + b1) -> a3[:, :64]
    for (int idx = tid; idx < 128 * 64; idx += NT) {
        int p = idx >> 6, c = idx & 63;
        float v = fmaf(xs[p * 3 + 2], w1s[c * 3 + 2],
                  fmaf(xs[p * 3 + 1], w1s[c * 3 + 1],
                  fmaf(xs[p * 3 + 0], w1s[c * 3 + 0], b1s[c])));
        a3[p * 130 + c] = frelu(v);
    }
    __syncthreads();

    stsW16<64, 64>(Wb, rw);
    ldgW16<64, 64>(rw, W3, 64, 0, 0);     // prefetch W3 chunk0
    __syncthreads();

    const int opg = tid >> 3;  // 0..31
    const int ocg = tid & 7;   // 0..7
    const int oc0 = ocg * 8;

    // ---- block2: h = relu(a1 @ W2^T + b2) -> hbuf
    {
        u64 acc[4][4];
#pragma unroll
        for (int i = 0; i < 4; i++)
#pragma unroll
            for (int j = 0; j < 4; j++) acc[i][j] = pack2(b2s[oc0 + 2 * j], b2s[oc0 + 2 * j + 1]);
        mma2<4, 32, 64, 64>(a3, 130, Wb, opg, ocg, acc);
#pragma unroll
        for (int i = 0; i < 4; i++)
#pragma unroll
            for (int j = 0; j < 4; j++) {
                float2 f = unpack2(acc[i][j]);
                hbuf[(opg + i * 32) * 68 + oc0 + 2 * j]     = frelu(f.x);
                hbuf[(opg + i * 32) * 68 + oc0 + 2 * j + 1] = frelu(f.y);
            }
    }
    __syncthreads();

    stsW16<64, 64>(Wb, rw);
    ldgW16<64, 64>(rw, W3, 64, 64, 0);    // prefetch W3 chunk1
    __syncthreads();

    // write h to global (needed by the back half)
    for (int idx = tid; idx < 128 * 64; idx += NT) {
        int p = idx >> 6, c = idx & 63;
        g_h[(pbase + p) * 64 + c] = hbuf[p * 68 + c];
    }

    // ---- block3 chunk 0: a3[:, :64]
    {
        u64 acc[4][4];
#pragma unroll
        for (int i = 0; i < 4; i++)
#pragma unroll
            for (int j = 0; j < 4; j++) acc[i][j] = pack2(b3s[oc0 + 2 * j], b3s[oc0 + 2 * j + 1]);
        mma2<4, 32, 64, 64>(hbuf, 68, Wb, opg, ocg, acc);
#pragma unroll
        for (int i = 0; i < 4; i++)
#pragma unroll
            for (int j = 0; j < 4; j++) {
                float2 f = unpack2(acc[i][j]);
                a3[(opg + i * 32) * 130 + oc0 + 2 * j]     = frelu(f.x);
                a3[(opg + i * 32) * 130 + oc0 + 2 * j + 1] = frelu(f.y);
            }
    }
    __syncthreads();

    stsW16<64, 64>(Wb, rw);
    ldgWn<32, 128>(rw, W4, 128, 0, 0);    // prefetch W4 slab 0 (new layout)
    __syncthreads();

    // ---- block3 chunk 1: a3[:, 64:]
    {
        u64 acc[4][4];
#pragma unroll
        for (int i = 0; i < 4; i++)
#pragma unroll
            for (int j = 0; j < 4; j++) acc[i][j] = pack2(b3s[64 + oc0 + 2 * j], b3s[64 + oc0 + 2 * j + 1]);
        mma2<4, 32, 64, 64>(hbuf, 68, Wb, opg, ocg, acc);
#pragma unroll
        for (int i = 0; i < 4; i++)
#pragma unroll
            for (int j = 0; j < 4; j++) {
                float2 f = unpack2(acc[i][j]);
                a3[(opg + i * 32) * 130 + 64 + oc0 + 2 * j]     = frelu(f.x);
                a3[(opg + i * 32) * 130 + 64 + oc0 + 2 * j + 1] = frelu(f.y);
            }
    }

    // ---- block4 (wide): 8 passes x 128 out-ch, K=128 in 4 slabs of KS=32.
    // tile 8pt x 8ch: warp = 16 pgrp x 2 cgrp -> conflict-free LDS.
    const int pgrp = (tid & 31) >> 1;            // 0..15, PGR=16
    const int cgrp = (tid >> 5) * 2 + (tid & 1); // 0..15
    for (int cc = 0; cc < 8; cc++) {
        u64 acc[8][4];
#pragma unroll
        for (int q = 0; q < 4; q++) {
            float2 bb = __ldg((const float2*)(b4 + cc * 128 + cgrp * 8 + 2 * q));
            u64 bv = pack2(bb.x, bb.y);
#pragma unroll
            for (int i = 0; i < 8; i++) acc[i][q] = bv;
        }
        for (int s = 0; s < 4; s++) {
            __syncthreads();
            stsWn<32, 128>(Wb, rw);
            int t = cc * 4 + s + 1;
            if (t < 32) ldgWn<32, 128>(rw, W4, 128, (t >> 2) * 128, (t & 3) * 32);
            __syncthreads();
            mmaW<8, 16, 8, 32>(a3 + s * 32, 130, Wb, 132, pgrp, cgrp, acc);
        }
        // epilogue: in-thread max over 8 points, shfl tree over pgrp bits, 2 lanes atomic
        float mx[8];
#pragma unroll
        for (int q = 0; q < 4; q++) {
            float2 f = unpack2(acc[0][q]);
            mx[2 * q] = f.x; mx[2 * q + 1] = f.y;
        }
#pragma unroll
        for (int i = 1; i < 8; i++)
#pragma unroll
            for (int q = 0; q < 4; q++) {
                float2 f = unpack2(acc[i][q]);
                mx[2 * q]     = fmaxf(mx[2 * q], f.x);
                mx[2 * q + 1] = fmaxf(mx[2 * q + 1], f.y);
            }
#pragma unroll
        for (int m = 2; m < 32; m <<= 1)
#pragma unroll
            for (int j = 0; j < 8; j++)
                mx[j] = fmaxf(mx[j], __shfl_xor_sync(0xffffffffu, mx[j], m));
        if ((tid & 31) < 2) {
#pragma unroll
            for (int j = 0; j < 8; j++)
                atomicMax(&gmax[cc * 128 + cgrp * 8 + j], __float_as_int(frelu(mx[j])));
        }
    }
    __syncthreads();
    for (int i = tid; i < 1024; i += NT) atomicMax(&g_gmax[i], gmax[i]);
}

// ============================================================
// Kernel B: c5[j] = b5[j] + sum_i W5[j][64+i] * g[i]
// ============================================================
__global__ void k_c5(const float* __restrict__ W5, const float* __restrict__ b5) {
    __shared__ float gs[1024];
    const int tid = threadIdx.x;
    for (int i = tid; i < 1024; i += 256) gs[i] = __int_as_float(g_gmax[i]);
    __syncthreads();
    const int j = blockIdx.x * 64 + (tid >> 2);
    const int q = tid & 3;
    const float* wr = W5 + j * 1088 + 64 + q * 256;
    const float* gr = gs + q * 256;
    float s = 0.f;
#pragma unroll 8
    for (int i = 0; i < 256; i++) s = fmaf(wr[i], gr[i], s);
    s += __shfl_xor_sync(0xffffffffu, s, 1);
    s += __shfl_xor_sync(0xffffffffu, s, 2);
    if (q == 0) g_c5[j] = s + b5[j];
}

// ============================================================
// Kernel C: blocks 5..8 fused, wide tiles. CTA = 64 pts, 256 thr.
// warp = 8 pgrp x 4 cgrp. smem: z5[64*516] z6[64*260] Wb[4224] w8s[129]
// (hbuf overlays z6 during block5; z7 overlays z5 after block6)
// ============================================================
#define SMEM3_FLOATS (64 * 516 + 64 * 260 + 4224 + 129)

__global__ __launch_bounds__(NT, 1) void k_back(
    const float* __restrict__ W5,
    const float* __restrict__ W6, const float* __restrict__ b6,
    const float* __restrict__ W7, const float* __restrict__ b7,
    const float* __restrict__ W8, const float* __restrict__ b8,
    float* __restrict__ out) {
    extern __shared__ float sm[];
    float* z5   = sm;                  // [64][516]
    float* z6   = z5 + 64 * 516;       // [64][260]
    float* Wb   = z6 + 64 * 260;       // 4224 floats
    float* w8s  = Wb + 4224;           // 128 + 1
    float* hbuf = z6;                  // stride 68 overlay during block5

    const int tid   = threadIdx.x;
    const int pbase = blockIdx.x * 64;

    for (int i = tid; i < 128; i += NT) w8s[i] = W8[i];
    if (tid == 0) w8s[128] = b8[0];
    for (int idx = tid; idx < 64 * 64; idx += NT) {
        int p = idx >> 6, c = idx & 63;
        hbuf[p * 68 + c] = g_h[(pbase + p) * 64 + c];
    }

    float rw[16];
    ldgWn<16, 256>(rw, W5, 1088, 0, 0);   // prefetch W5 slab 0
    __syncthreads();

    const int pgrp = (tid & 31) >> 2;            // 0..7, PGR=8
    const int cgrp = (tid >> 5) * 4 + (tid & 3); // 0..31

    // ---- block5: z5 = relu(h @ W5a^T + c5). 2 passes x 256 ch, K=64 (4 slabs KS=16)
    for (int cc = 0; cc < 2; cc++) {
        u64 acc[8][4];
#pragma unroll
        for (int q = 0; q < 4; q++) {
            float2 bb = __ldg((const float2*)(g_c5 + cc * 256 + cgrp * 8 + 2 * q));
            u64 bv = pack2(bb.x, bb.y);
#pragma unroll
            for (int i = 0; i < 8; i++) acc[i][q] = bv;
        }
        for (int s = 0; s < 4; s++) {
            __syncthreads();
            stsWn<16, 256>(Wb, rw);
            int t = cc * 4 + s + 1;
            if (t < 8)       ldgWn<16, 256>(rw, W5, 1088, (t >> 2) * 256, (t & 3) * 16);
            else if (t == 8) ldgWn<16, 256>(rw, W6, 512, 0, 0);
            __syncthreads();
            mmaW<8, 8, 8, 16>(hbuf + s * 16, 68, Wb, 260, pgrp, cgrp, acc);
        }
#pragma unroll
        for (int i = 0; i < 8; i++) {
            float* zp = z5 + (pgrp + 8 * i) * 516 + cc * 256 + cgrp * 8;
            float2 f0 = unpack2(acc[i][0]), f1 = unpack2(acc[i][1]);
            *(float4*)zp = make_float4(frelu(f0.x), frelu(f0.y), frelu(f1.x), frelu(f1.y));
            f0 = unpack2(acc[i][2]); f1 = unpack2(acc[i][3]);
            *(float4*)(zp + 4) = make_float4(frelu(f0.x), frelu(f0.y), frelu(f1.x), frelu(f1.y));
        }
    }

    // ---- block6: z6 = relu(z5 @ W6^T + b6). 256 ch one pass, K=512 (32 slabs KS=16)
    {
        u64 acc[8][4];
#pragma unroll
        for (int q = 0; q < 4; q++) {
            float2 bb = __ldg((const float2*)(b6 + cgrp * 8 + 2 * q));
            u64 bv = pack2(bb.x, bb.y);
#pragma unroll
            for (int i = 0; i < 8; i++) acc[i][q] = bv;
        }
        for (int s = 0; s < 32; s++) {
            __syncthreads();
            stsWn<16, 256>(Wb, rw);
            int t = s + 1;
            if (t < 32) ldgWn<16, 256>(rw, W6, 512, 0, t * 16);
            else        ldgWn<32, 128>(rw, W7, 256, 0, 0);
            __syncthreads();
            mmaW<8, 8, 8, 16>(z5 + s * 16, 516, Wb, 260, pgrp, cgrp, acc);
        }
#pragma unroll
        for (int i = 0; i < 8; i++) {
            float* zp = z6 + (pgrp + 8 * i) * 260 + cgrp * 8;
            float2 f0 = unpack2(acc[i][0]), f1 = unpack2(acc[i][1]);
            *(float4*)zp = make_float4(frelu(f0.x), frelu(f0.y), frelu(f1.x), frelu(f1.y));
            f0 = unpack2(acc[i][2]); f1 = unpack2(acc[i][3]);
            *(float4*)(zp + 4) = make_float4(frelu(f0.x), frelu(f0.y), frelu(f1.x), frelu(f1.y));
        }
    }

    // ---- block7: z7 = relu(z6 @ W7^T + b7). 128 ch (TC=4), K=256 (8 slabs KS=32)
    {
        u64 acc[8][2];
#pragma unroll
        for (int q = 0; q < 2; q++) {
            float2 bb = __ldg((const float2*)(b7 + cgrp * 4 + 2 * q));
            u64 bv = pack2(bb.x, bb.y);
#pragma unroll
            for (int i = 0; i < 8; i++) acc[i][q] = bv;
        }
        for (int s = 0; s < 8; s++) {
            __syncthreads();
            stsWn<32, 128>(Wb, rw);
            if (s < 7) ldgWn<32, 128>(rw, W7, 256, 0, (s + 1) * 32);
            __syncthreads();
            mmaW<8, 8, 4, 32>(z6 + s * 32, 260, Wb, 132, pgrp, cgrp, acc);
        }
        // z7 overlays z5 (stride 516, cols 0..127)
#pragma unroll
        for (int i = 0; i < 8; i++) {
            float2 f0 = unpack2(acc[i][0]), f1 = unpack2(acc[i][1]);
            *(float4*)(z5 + (pgrp + 8 * i) * 516 + cgrp * 4) =
                make_float4(frelu(f0.x), frelu(f0.y), frelu(f1.x), frelu(f1.y));
        }
    }
    __syncthreads();

    // ---- block8: out = z7 @ W8^T + b8 (no relu)
    if (tid < 64) {
        const float* zr = z5 + tid * 516;
        float s = w8s[128];
#pragma unroll 8
        for (int k = 0; k < 128; k++) s = fmaf(zr[k], w8s[k], s);
        out[pbase + tid] = s;
    }
}

// ============================================================
extern "C" void kernel_launch(void* const* d_in, const int* in_sizes, int n_in,
                              void* d_out, int out_size) {
    const float* x  = (const float*)d_in[0];
    const float* W1 = (const float*)d_in[1];  const float* b1 = (const float*)d_in[2];
    const float* W2 = (const float*)d_in[3];  const float* b2 = (const float*)d_in[4];
    const float* W3 = (const float*)d_in[5];  const float* b3 = (const float*)d_in[6];
    const float* W4 = (const float*)d_in[7];  const float* b4 = (const float*)d_in[8];
    const float* W5 = (const float*)d_in[9];  const float* b5 = (const float*)d_in[10];
    const float* W6 = (const float*)d_in[11]; const float* b6 = (const float*)d_in[12];
    const float* W7 = (const float*)d_in[13]; const float* b7 = (const float*)d_in[14];
    const float* W8 = (const float*)d_in[15]; const float* b8 = (const float*)d_in[16];
    float* out = (float*)d_out;

    const int n = in_sizes[0] / 3;  // 65536

    const int smem1 = SMEM1_FLOATS * (int)sizeof(float);
    const int smem3 = SMEM3_FLOATS * (int)sizeof(float);
    cudaFuncSetAttribute(k_front, cudaFuncAttributeMaxDynamicSharedMemorySize, smem1);
    cudaFuncSetAttribute(k_back,  cudaFuncAttributeMaxDynamicSharedMemorySize, smem3);

    k_init<<<1, 1024>>>();
    k_front<<<n / 128, NT, smem1>>>(x, W1, b1, W2, b2, W3, b3, W4, b4);
    k_c5<<<8, 256>>>(W5, b5);
    k_back<<<n / 64, NT, smem3>>>(W5, W6, b6, W7, b7, W8, b8, out);
}

// round 7
// speedup vs baseline: 2.4785x; 1.6669x over previous
#include <cuda_runtime.h>
#include <cuda_bf16.h>
#include <cstdint>

#define NT 256

typedef unsigned long long u64;

// -------- persistent device scratch (no allocs allowed) --------
__device__ float g_h[65536 * 64];   // h = block2 output, needed for skip-concat
__device__ int   g_gmax[1024];      // global max-pool accumulator (float bits, >=0)
__device__ float g_c5[512];         // c5 = b5 + W5[:,64:] @ g

__device__ __forceinline__ float frelu(float v) { return v > 0.f ? v : 0.f; }

// ---- packed f32x2 helpers (FFMA2, for the small SIMT blocks) ----
__device__ __forceinline__ u64 fma2(u64 a, u64 b, u64 c) {
    u64 d; asm("fma.rn.f32x2 %0, %1, %2, %3;" : "=l"(d) : "l"(a), "l"(b), "l"(c)); return d;
}
__device__ __forceinline__ u64 splat2(float a) {
    u64 d; asm("mov.b64 %0, {%1, %1};" : "=l"(d) : "f"(a)); return d;
}
__device__ __forceinline__ u64 pack2(float lo, float hi) {
    u64 d; asm("mov.b64 %0, {%1, %2};" : "=l"(d) : "f"(lo), "f"(hi)); return d;
}
__device__ __forceinline__ float2 unpack2(u64 v) {
    float2 f; asm("mov.b64 {%0, %1}, %2;" : "=f"(f.x), "=f"(f.y) : "l"(v)); return f;
}

// ============================================================
// HMMA (mma.sync) machinery — compiles at plain sm_103 target.
// D[16x8] += A[16x16] * B[16x8], bf16 in, f32 accum, row.col.
// ============================================================
__device__ __forceinline__ void mma16816(float* c, const uint32_t* a, const uint32_t* b) {
    asm volatile(
        "mma.sync.aligned.m16n8k16.row.col.f32.bf16.bf16.f32 "
        "{%0,%1,%2,%3}, {%4,%5,%6,%7}, {%8,%9}, {%0,%1,%2,%3};"
        : "+f"(c[0]), "+f"(c[1]), "+f"(c[2]), "+f"(c[3])
        : "r"(a[0]), "r"(a[1]), "r"(a[2]), "r"(a[3]), "r"(b[0]), "r"(b[1]));
}
__device__ __forceinline__ void ldsm4(uint32_t r[4], uint32_t addr) {
    asm volatile("ldmatrix.sync.aligned.m8n8.x4.shared.b16 {%0,%1,%2,%3}, [%4];"
                 : "=r"(r[0]), "=r"(r[1]), "=r"(r[2]), "=r"(r[3]) : "r"(addr));
}
__device__ __forceinline__ uint32_t smem_to_u32(const void* p) {
    uint32_t a;
    asm("{ .reg .u64 t; cvta.to.shared.u64 t, %1; cvt.u32.u64 %0, t; }" : "=r"(a) : "l"(p));
    return a;
}

// split a float2 into packed bf16x2 hi and lo (residual) parts.
// hi reg: low 16 bits = bf16(v.x), high = bf16(v.y) (memory order).
__device__ __forceinline__ void split2(float2 v, uint32_t& hi, uint32_t& lo) {
    uint32_t h;
    asm("cvt.rn.bf16x2.f32 %0, %1, %2;" : "=r"(h) : "f"(v.y), "f"(v.x));
    float h0 = __uint_as_float(h << 16);
    float h1 = __uint_as_float(h & 0xFFFF0000u);
    float l0 = v.x - h0, l1 = v.y - h1;
    asm("cvt.rn.bf16x2.f32 %0, %1, %2;" : "=r"(lo) : "f"(l1), "f"(l0));
    hi = h;
}

// Load one 16x16 A tile (rows row0.., k kabs..) from fp32 smem as hi/lo frags.
__device__ __forceinline__ void ldAfrag(const float* __restrict__ A, int SA, int row0,
                                        int kabs, int lane,
                                        uint32_t ahi[4], uint32_t alo[4]) {
    int g = lane >> 2, t = lane & 3;
    const float* base = A + (size_t)(row0 + g) * SA + kabs + 2 * t;
    float2 v0 = *(const float2*)(base);
    float2 v1 = *(const float2*)(base + 8 * SA);
    float2 v2 = *(const float2*)(base + 8);
    float2 v3 = *(const float2*)(base + 8 * SA + 8);
    split2(v0, ahi[0], alo[0]);
    split2(v1, ahi[1], alo[1]);
    split2(v2, ahi[2], alo[2]);
    split2(v3, ahi[3], alo[3]);
}

// One k16 step of warp GEMM: 32 rows x (NTILES*16) cols, 3-term bf16 split.
// A: fp32 smem (stride SA). W slab: bf16 halves in smem, row stride SWB halves.
template <int NTILES>
__device__ __forceinline__ void gemm_kstep(const float* __restrict__ A, int SA, int m0,
                                           uint32_t whi, uint32_t wlo, int SWB,
                                           int n0loc, int k0loc, int kabs, int lane,
                                           float acc[2][NTILES * 2][4]) {
    uint32_t ahi[2][4], alo[2][4];
    ldAfrag(A, SA, m0,      kabs, lane, ahi[0], alo[0]);
    ldAfrag(A, SA, m0 + 16, kabs, lane, ahi[1], alo[1]);
    uint32_t bh[NTILES][4], bl[NTILES][4];
    const int nl = n0loc + (lane & 7) + ((lane >> 4) << 3);
    const int kk = k0loc + (((lane >> 3) & 1) << 3);
#pragma unroll
    for (int nt = 0; nt < NTILES; nt++) {
        uint32_t off = (uint32_t)((nl + nt * 16) * SWB + kk) * 2;
        ldsm4(bh[nt], whi + off);
        ldsm4(bl[nt], wlo + off);
    }
#pragma unroll
    for (int mi = 0; mi < 2; mi++)
#pragma unroll
        for (int nt = 0; nt < NTILES; nt++) {
            mma16816(acc[mi][2 * nt],     ahi[mi], &bh[nt][0]);
            mma16816(acc[mi][2 * nt + 1], ahi[mi], &bh[nt][2]);
        }
#pragma unroll
    for (int mi = 0; mi < 2; mi++)
#pragma unroll
        for (int nt = 0; nt < NTILES; nt++) {
            mma16816(acc[mi][2 * nt],     ahi[mi], &bl[nt][0]);
            mma16816(acc[mi][2 * nt + 1], ahi[mi], &bl[nt][2]);
        }
#pragma unroll
    for (int mi = 0; mi < 2; mi++)
#pragma unroll
        for (int nt = 0; nt < NTILES; nt++) {
            mma16816(acc[mi][2 * nt],     alo[mi], &bh[nt][0]);
            mma16816(acc[mi][2 * nt + 1], alo[mi], &bh[nt][2]);
        }
}

// Weight slab staging: global fp32 -> smem bf16 hi/lo, k-major rows, +8-half pad.
// Slab = C rows x KF k (C*KF == 4096). Prefetch into 8 float2 regs, then split+STS.
template <int C, int KF>
__device__ __forceinline__ void ldgS(float2 rw[8], const float* __restrict__ W,
                                     int ldW, int cbase, int kbase) {
    static_assert(C * KF == 16 * NT, "slab size");
    constexpr int KF2 = KF / 2;
#pragma unroll
    for (int j = 0; j < 8; j++) {
        int idx = threadIdx.x + j * NT;
        int c = idx / KF2, k2 = idx % KF2;
        rw[j] = *(const float2*)(W + (size_t)(cbase + c) * ldW + kbase + 2 * k2);
    }
}
template <int C, int KF>
__device__ __forceinline__ void stsS(uint32_t* __restrict__ whi32,
                                     uint32_t* __restrict__ wlo32, const float2 rw[8]) {
    constexpr int KF2 = KF / 2;
    constexpr int SWB32 = (KF + 8) / 2;
#pragma unroll
    for (int j = 0; j < 8; j++) {
        int idx = threadIdx.x + j * NT;
        int c = idx / KF2, k2 = idx % KF2;
        uint32_t hi, lo;
        split2(rw[j], hi, lo);
        whi32[c * SWB32 + k2] = hi;
        wlo32[c * SWB32 + k2] = lo;
    }
}

// Epilogue: relu(acc + bias) -> fp32 smem Z (stride SZ), cols nbase..
template <int NJ>
__device__ __forceinline__ void epi_store(float* __restrict__ Z, int SZ, int m0, int nbase,
                                          const float* __restrict__ bias,
                                          float acc[2][NJ][4], int lane) {
    int g = lane >> 2, t = lane & 3;
#pragma unroll
    for (int mi = 0; mi < 2; mi++)
#pragma unroll
        for (int nj = 0; nj < NJ; nj++) {
            int col = nbase + nj * 8 + 2 * t;
            float2 b = __ldg((const float2*)(bias + col));
            int row = m0 + mi * 16 + g;
            float2 v0 = make_float2(frelu(acc[mi][nj][0] + b.x), frelu(acc[mi][nj][1] + b.y));
            float2 v1 = make_float2(frelu(acc[mi][nj][2] + b.x), frelu(acc[mi][nj][3] + b.y));
            *(float2*)(Z + (size_t)row * SZ + col) = v0;
            *(float2*)(Z + (size_t)(row + 8) * SZ + col) = v1;
        }
}

// ---- small-tile SIMT path (blocks 1-3) ----
template <int KS, int CW>
__device__ __forceinline__ void ldgW16(float r[16], const float* __restrict__ W,
                                       int ldW, int cbase, int kbase) {
#pragma unroll
    for (int j = 0; j < 16; j++) {
        int idx = threadIdx.x + j * NT;
        int c = idx / KS, k = idx % KS;
        r[j] = __ldg(W + (cbase + c) * ldW + (kbase + k));
    }
}
template <int KS, int CW>
__device__ __forceinline__ void stsW16(float* __restrict__ Wb, const float r[16]) {
#pragma unroll
    for (int j = 0; j < 16; j++) {
        int idx = threadIdx.x + j * NT;
        int c = idx / KS, k = idx % KS;
        Wb[k * (CW + 4) + c] = r[j];
    }
}
template <int TP, int PGR, int CW, int KS>
__device__ __forceinline__ void mma2(const float* __restrict__ A, int SA,
                                     const float* __restrict__ Wb,
                                     int pgrp, int cgrp, u64 acc[TP][4]) {
    constexpr int SWB = CW + 4;
    const float* Ap[TP];
#pragma unroll
    for (int i = 0; i < TP; i++) Ap[i] = A + (pgrp + i * PGR) * SA;
    const char* wbase = (const char*)(Wb + cgrp * 8);
#pragma unroll 8
    for (int k = 0; k < KS; k++) {
        ulonglong2 u0 = *(const ulonglong2*)(wbase + (size_t)k * (SWB * 4));
        ulonglong2 u1 = *(const ulonglong2*)(wbase + (size_t)k * (SWB * 4) + 16);
#pragma unroll
        for (int i = 0; i < TP; i++) {
            u64 a2 = splat2(Ap[i][k]);
            acc[i][0] = fma2(a2, u0.x, acc[i][0]);
            acc[i][1] = fma2(a2, u0.y, acc[i][1]);
            acc[i][2] = fma2(a2, u1.x, acc[i][2]);
            acc[i][3] = fma2(a2, u1.y, acc[i][3]);
        }
    }
}

// -------- init: reset max-pool accumulator each replay --------
__global__ void k_init() {
    g_gmax[threadIdx.x] = 0;  // relu outputs >= 0, so float bits 0 is identity
}

// ============================================================
// Kernel A: blocks 1..3 SIMT + block4 via HMMA 3xBF16 split.
// CTA = 128 points, 256 threads.
// smem floats:
//   a3    [128*132] @ 0       (16896)
//   hbuf  [128*68]  @ 16896   (8704)
//   Wb    [64*68]   @ 25600   (4352)   SIMT W2/W3 slabs
//   Wslab hi/lo     @ 29952   (6144)   bf16 halves, 3072 u32 each
//   gmax  [1024]    @ 36096
//   consts          @ 37120   (832)
// ============================================================
#define SMEM1_FLOATS 37952

__global__ __launch_bounds__(NT, 1) void k_front(
    const float* __restrict__ x,
    const float* __restrict__ W1, const float* __restrict__ b1,
    const float* __restrict__ W2, const float* __restrict__ b2,
    const float* __restrict__ W3, const float* __restrict__ b3,
    const float* __restrict__ W4, const float* __restrict__ b4) {
    extern __shared__ float sm[];
    float* a3   = sm;
    float* hbuf = sm + 16896;
    float* Wb   = sm + 25600;
    uint32_t* whi32 = (uint32_t*)(sm + 29952);
    uint32_t* wlo32 = whi32 + 3072;
    int*   gmax = (int*)(sm + 36096);
    float* cst  = sm + 37120;
    float* w1s = cst;          // 192
    float* b1s = cst + 192;    // 64
    float* xs  = cst + 256;    // 384
    float* b2s = cst + 640;    // 64
    float* b3s = cst + 704;    // 128

    const int tid   = threadIdx.x;
    const int wid   = tid >> 5;
    const int lane  = tid & 31;
    const int pbase = blockIdx.x * 128;

    for (int i = tid; i < 1024; i += NT) gmax[i] = 0;
    for (int i = tid; i < 192; i += NT) w1s[i] = W1[i];
    for (int i = tid; i < 64; i += NT) { b1s[i] = b1[i]; b2s[i] = b2[i]; }
    for (int i = tid; i < 128; i += NT) b3s[i] = b3[i];
    for (int i = tid; i < 384; i += NT) xs[i] = x[pbase * 3 + i];

    float rw[16];
    ldgW16<64, 64>(rw, W2, 64, 0, 0);     // prefetch W2 slab
    __syncthreads();

    // ---- block1: a1 = relu(x @ W1^T + b1) -> a3[:, :64]
    for (int idx = tid; idx < 128 * 64; idx += NT) {
        int p = idx >> 6, c = idx & 63;
        float v = fmaf(xs[p * 3 + 2], w1s[c * 3 + 2],
                  fmaf(xs[p * 3 + 1], w1s[c * 3 + 1],
                  fmaf(xs[p * 3 + 0], w1s[c * 3 + 0], b1s[c])));
        a3[p * 132 + c] = frelu(v);
    }
    __syncthreads();

    stsW16<64, 64>(Wb, rw);
    ldgW16<64, 64>(rw, W3, 64, 0, 0);
    __syncthreads();

    const int opg = tid >> 3;  // 0..31
    const int ocg = tid & 7;   // 0..7
    const int oc0 = ocg * 8;

    // ---- block2: h = relu(a1 @ W2^T + b2) -> hbuf
    {
        u64 acc[4][4];
#pragma unroll
        for (int i = 0; i < 4; i++)
#pragma unroll
            for (int j = 0; j < 4; j++) acc[i][j] = pack2(b2s[oc0 + 2 * j], b2s[oc0 + 2 * j + 1]);
        mma2<4, 32, 64, 64>(a3, 132, Wb, opg, ocg, acc);
#pragma unroll
        for (int i = 0; i < 4; i++)
#pragma unroll
            for (int j = 0; j < 4; j++) {
                float2 f = unpack2(acc[i][j]);
                hbuf[(opg + i * 32) * 68 + oc0 + 2 * j]     = frelu(f.x);
                hbuf[(opg + i * 32) * 68 + oc0 + 2 * j + 1] = frelu(f.y);
            }
    }
    __syncthreads();

    stsW16<64, 64>(Wb, rw);
    ldgW16<64, 64>(rw, W3, 64, 64, 0);
    __syncthreads();

    // write h to global (needed by the back half)
    for (int idx = tid; idx < 128 * 64; idx += NT) {
        int p = idx >> 6, c = idx & 63;
        g_h[(pbase + p) * 64 + c] = hbuf[p * 68 + c];
    }

    // ---- block3 chunk 0: a3[:, :64]
    {
        u64 acc[4][4];
#pragma unroll
        for (int i = 0; i < 4; i++)
#pragma unroll
            for (int j = 0; j < 4; j++) acc[i][j] = pack2(b3s[oc0 + 2 * j], b3s[oc0 + 2 * j + 1]);
        mma2<4, 32, 64, 64>(hbuf, 68, Wb, opg, ocg, acc);
#pragma unroll
        for (int i = 0; i < 4; i++)
#pragma unroll
            for (int j = 0; j < 4; j++) {
                float2 f = unpack2(acc[i][j]);
                a3[(opg + i * 32) * 132 + oc0 + 2 * j]     = frelu(f.x);
                a3[(opg + i * 32) * 132 + oc0 + 2 * j + 1] = frelu(f.y);
            }
    }
    __syncthreads();

    stsW16<64, 64>(Wb, rw);
    float2 rw2[8];
    ldgS<128, 32>(rw2, W4, 128, 0, 0);   // prefetch W4 slab(0,0)
    __syncthreads();

    // ---- block3 chunk 1: a3[:, 64:]
    {
        u64 acc[4][4];
#pragma unroll
        for (int i = 0; i < 4; i++)
#pragma unroll
            for (int j = 0; j < 4; j++) acc[i][j] = pack2(b3s[64 + oc0 + 2 * j], b3s[64 + oc0 + 2 * j + 1]);
        mma2<4, 32, 64, 64>(hbuf, 68, Wb, opg, ocg, acc);
#pragma unroll
        for (int i = 0; i < 4; i++)
#pragma unroll
            for (int j = 0; j < 4; j++) {
                float2 f = unpack2(acc[i][j]);
                a3[(opg + i * 32) * 132 + 64 + oc0 + 2 * j]     = frelu(f.x);
                a3[(opg + i * 32) * 132 + 64 + oc0 + 2 * j + 1] = frelu(f.y);
            }
    }

    // ---- block4: 8 chunks of 128 out-ch via HMMA; only channel max kept.
    const uint32_t whi_a = smem_to_u32(whi32);
    const uint32_t wlo_a = smem_to_u32(wlo32);
    const int m0 = (wid & 3) * 32;   // 4 M-warps
    const int n0 = (wid >> 2) * 64;  // 2 N-warps

    for (int cc = 0; cc < 8; cc++) {
        float acc[2][8][4];
#pragma unroll
        for (int mi = 0; mi < 2; mi++)
#pragma unroll
            for (int nj = 0; nj < 8; nj++)
#pragma unroll
                for (int q = 0; q < 4; q++) acc[mi][nj][q] = 0.f;

        for (int s = 0; s < 4; s++) {
            __syncthreads();
            stsS<128, 32>(whi32, wlo32, rw2);
            int t = cc * 4 + s + 1;
            if (t < 32) ldgS<128, 32>(rw2, W4, 128, (t >> 2) * 128, (t & 3) * 32);
            __syncthreads();
            gemm_kstep<4>(a3, 132, m0, whi_a, wlo_a, 40, n0, 0,  s * 32,      lane, acc);
            gemm_kstep<4>(a3, 132, m0, whi_a, wlo_a, 40, n0, 16, s * 32 + 16, lane, acc);
        }

        // epilogue: in-thread max over rows, shfl over groups, bias+relu, atomicMax
        float m0v[8], m1v[8];
#pragma unroll
        for (int nj = 0; nj < 8; nj++) {
            m0v[nj] = fmaxf(fmaxf(acc[0][nj][0], acc[0][nj][2]),
                            fmaxf(acc[1][nj][0], acc[1][nj][2]));
            m1v[nj] = fmaxf(fmaxf(acc[0][nj][1], acc[0][nj][3]),
                            fmaxf(acc[1][nj][1], acc[1][nj][3]));
        }
#pragma unroll
        for (int m = 4; m < 32; m <<= 1)
#pragma unroll
            for (int nj = 0; nj < 8; nj++) {
                m0v[nj] = fmaxf(m0v[nj], __shfl_xor_sync(0xffffffffu, m0v[nj], m));
                m1v[nj] = fmaxf(m1v[nj], __shfl_xor_sync(0xffffffffu, m1v[nj], m));
            }
        if ((lane >> 2) == 0) {
            int t = lane & 3;
#pragma unroll
            for (int nj = 0; nj < 8; nj++) {
                int col = cc * 128 + n0 + nj * 8 + 2 * t;
                float2 b = __ldg((const float2*)(b4 + col));
                atomicMax(&gmax[col],     __float_as_int(frelu(m0v[nj] + b.x)));
                atomicMax(&gmax[col + 1], __float_as_int(frelu(m1v[nj] + b.y)));
            }
        }
    }
    __syncthreads();
    for (int i = tid; i < 1024; i += NT) atomicMax(&g_gmax[i], gmax[i]);
}

// ============================================================
// Kernel B: c5[j] = b5[j] + sum_i W5[j][64+i] * g[i]
// ============================================================
__global__ void k_c5(const float* __restrict__ W5, const float* __restrict__ b5) {
    __shared__ float gs[1024];
    const int tid = threadIdx.x;
    for (int i = tid; i < 1024; i += 256) gs[i] = __int_as_float(g_gmax[i]);
    __syncthreads();
    const int j = blockIdx.x * 64 + (tid >> 2);
    const int q = tid & 3;
    const float* wr = W5 + j * 1088 + 64 + q * 256;
    const float* gr = gs + q * 256;
    float s = 0.f;
#pragma unroll 8
    for (int i = 0; i < 256; i++) s = fmaf(wr[i], gr[i], s);
    s += __shfl_xor_sync(0xffffffffu, s, 1);
    s += __shfl_xor_sync(0xffffffffu, s, 2);
    if (q == 0) g_c5[j] = s + b5[j];
}

// ============================================================
// Kernel C: blocks 5..8 fused via HMMA. CTA = 64 pts, 256 thr.
// smem floats:
//   z5   [64*516] @ 0       (33024)   (z7 overlays cols 0..127)
//   z6   [64*260] @ 33024   (16640)   (hbuf [64][68] overlays start)
//   Wslab hi/lo   @ 49664   (6144)
//   w8s  [129]    @ 55808
// ============================================================
#define SMEM3_FLOATS 55937

__global__ __launch_bounds__(NT, 1) void k_back(
    const float* __restrict__ W5,
    const float* __restrict__ W6, const float* __restrict__ b6,
    const float* __restrict__ W7, const float* __restrict__ b7,
    const float* __restrict__ W8, const float* __restrict__ b8,
    float* __restrict__ out) {
    extern __shared__ float sm[];
    float* z5   = sm;
    float* z6   = sm + 33024;
    float* hbuf = z6;                  // stride 68 overlay during block5
    uint32_t* whi32 = (uint32_t*)(sm + 49664);
    uint32_t* wlo32 = whi32 + 3072;
    float* w8s = sm + 55808;

    const int tid   = threadIdx.x;
    const int wid   = tid >> 5;
    const int lane  = tid & 31;
    const int pbase = blockIdx.x * 64;

    for (int i = tid; i < 128; i += NT) w8s[i] = W8[i];
    if (tid == 0) w8s[128] = b8[0];
    for (int idx = tid; idx < 64 * 64; idx += NT) {
        int p = idx >> 6, c = idx & 63;
        hbuf[p * 68 + c] = g_h[(pbase + p) * 64 + c];
    }

    float2 rw2[8];
    ldgS<256, 16>(rw2, W5, 1088, 0, 0);   // W5a pass0 slab0 (h-part: k 0..63)
    __syncthreads();

    const uint32_t whi_a = smem_to_u32(whi32);
    const uint32_t wlo_a = smem_to_u32(wlo32);
    const int m0 = (wid & 1) * 32;   // 2 M-warps
    const int wn = wid >> 1;         // 4 N-warps

    // ---- block5: z5 = relu(h @ W5a^T + c5). 2 N-passes of 256, K=64.
    for (int cc = 0; cc < 2; cc++) {
        float acc[2][8][4];
#pragma unroll
        for (int mi = 0; mi < 2; mi++)
#pragma unroll
            for (int nj = 0; nj < 8; nj++)
#pragma unroll
                for (int q = 0; q < 4; q++) acc[mi][nj][q] = 0.f;
        for (int s = 0; s < 4; s++) {
            __syncthreads();
            stsS<256, 16>(whi32, wlo32, rw2);
            int t = cc * 4 + s + 1;
            if (t < 8)       ldgS<256, 16>(rw2, W5, 1088, (t >> 2) * 256, (t & 3) * 16);
            else if (t == 8) ldgS<256, 16>(rw2, W6, 512, 0, 0);
            __syncthreads();
            gemm_kstep<4>(hbuf, 68, m0, whi_a, wlo_a, 24, wn * 64, 0, s * 16, lane, acc);
        }
        epi_store<8>(z5, 516, m0, cc * 256 + wn * 64, g_c5, acc, lane);
    }

    // ---- block6: z6 = relu(z5 @ W6^T + b6). N=256, K=512.
    {
        float acc[2][8][4];
#pragma unroll
        for (int mi = 0; mi < 2; mi++)
#pragma unroll
            for (int nj = 0; nj < 8; nj++)
#pragma unroll
                for (int q = 0; q < 4; q++) acc[mi][nj][q] = 0.f;
        for (int s = 0; s < 32; s++) {
            __syncthreads();
            stsS<256, 16>(whi32, wlo32, rw2);
            int t = s + 1;
            if (t < 32) ldgS<256, 16>(rw2, W6, 512, 0, t * 16);
            else        ldgS<128, 32>(rw2, W7, 256, 0, 0);
            __syncthreads();
            gemm_kstep<4>(z5, 516, m0, whi_a, wlo_a, 24, wn * 64, 0, s * 16, lane, acc);
        }
        epi_store<8>(z6, 260, m0, wn * 64, b6, acc, lane);
    }

    // ---- block7: z7 = relu(z6 @ W7^T + b7). N=128, K=256. z7 overlays z5.
    {
        float acc[2][4][4];
#pragma unroll
        for (int mi = 0; mi < 2; mi++)
#pragma unroll
            for (int nj = 0; nj < 4; nj++)
#pragma unroll
                for (int q = 0; q < 4; q++) acc[mi][nj][q] = 0.f;
        for (int s = 0; s < 8; s++) {
            __syncthreads();
            stsS<128, 32>(whi32, wlo32, rw2);
            if (s < 7) ldgS<128, 32>(rw2, W7, 256, 0, (s + 1) * 32);
            __syncthreads();
            gemm_kstep<2>(z6, 260, m0, whi_a, wlo_a, 40, wn * 32, 0,  s * 32,      lane, acc);
            gemm_kstep<2>(z6, 260, m0, whi_a, wlo_a, 40, wn * 32, 16, s * 32 + 16, lane, acc);
        }
        __syncthreads();   // z5 (block6's A) dead; safe to overlay z7
        epi_store<4>(z5, 516, m0, wn * 32, b7, acc, lane);
    }
    __syncthreads();

    // ---- block8: out = z7 @ W8^T + b8 (no relu)
    if (tid < 64) {
        const float* zr = z5 + tid * 516;
        float s = w8s[128];
#pragma unroll 8
        for (int k = 0; k < 128; k++) s = fmaf(zr[k], w8s[k], s);
        out[pbase + tid] = s;
    }
}

// ============================================================
extern "C" void kernel_launch(void* const* d_in, const int* in_sizes, int n_in,
                              void* d_out, int out_size) {
    const float* x  = (const float*)d_in[0];
    const float* W1 = (const float*)d_in[1];  const float* b1 = (const float*)d_in[2];
    const float* W2 = (const float*)d_in[3];  const float* b2 = (const float*)d_in[4];
    const float* W3 = (const float*)d_in[5];  const float* b3 = (const float*)d_in[6];
    const float* W4 = (const float*)d_in[7];  const float* b4 = (const float*)d_in[8];
    const float* W5 = (const float*)d_in[9];  const float* b5 = (const float*)d_in[10];
    const float* W6 = (const float*)d_in[11]; const float* b6 = (const float*)d_in[12];
    const float* W7 = (const float*)d_in[13]; const float* b7 = (const float*)d_in[14];
    const float* W8 = (const float*)d_in[15]; const float* b8 = (const float*)d_in[16];
    float* out = (float*)d_out;

    const int n = in_sizes[0] / 3;  // 65536

    const int smem1 = SMEM1_FLOATS * (int)sizeof(float);
    const int smem3 = SMEM3_FLOATS * (int)sizeof(float);
    cudaFuncSetAttribute(k_front, cudaFuncAttributeMaxDynamicSharedMemorySize, smem1);
    cudaFuncSetAttribute(k_back,  cudaFuncAttributeMaxDynamicSharedMemorySize, smem3);

    k_init<<<1, 1024>>>();
    k_front<<<n / 128, NT, smem1>>>(x, W1, b1, W2, b2, W3, b3, W4, b4);
    k_c5<<<8, 256>>>(W5, b5);
    k_back<<<n / 64, NT, smem3>>>(W5, W6, b6, W7, b7, W8, b8, out);
}

// round 8
// speedup vs baseline: 2.8011x; 1.1302x over previous
#include <cuda_runtime.h>
#include <cuda_bf16.h>
#include <cstdint>

#define NT 256

typedef unsigned long long u64;

// -------- persistent device scratch (no allocs allowed) --------
__device__ float g_h[65536 * 64];   // h = block2 output, needed for skip-concat
__device__ int   g_gmax[1024];      // global max-pool accumulator (float bits, >=0)
__device__ float g_c5[512];         // c5 = b5 + W5[:,64:] @ g

__device__ __forceinline__ float frelu(float v) { return v > 0.f ? v : 0.f; }

// ---- packed f32x2 helpers (FFMA2, for the small SIMT blocks) ----
__device__ __forceinline__ u64 fma2(u64 a, u64 b, u64 c) {
    u64 d; asm("fma.rn.f32x2 %0, %1, %2, %3;" : "=l"(d) : "l"(a), "l"(b), "l"(c)); return d;
}
__device__ __forceinline__ u64 splat2(float a) {
    u64 d; asm("mov.b64 %0, {%1, %1};" : "=l"(d) : "f"(a)); return d;
}
__device__ __forceinline__ u64 pack2(float lo, float hi) {
    u64 d; asm("mov.b64 %0, {%1, %2};" : "=l"(d) : "f"(lo), "f"(hi)); return d;
}
__device__ __forceinline__ float2 unpack2(u64 v) {
    float2 f; asm("mov.b64 {%0, %1}, %2;" : "=f"(f.x), "=f"(f.y) : "l"(v)); return f;
}

// ============================================================
// HMMA (mma.sync) machinery — compiles at plain sm_103 target.
// ============================================================
__device__ __forceinline__ void mma16816(float* c, const uint32_t* a, const uint32_t* b) {
    asm volatile(
        "mma.sync.aligned.m16n8k16.row.col.f32.bf16.bf16.f32 "
        "{%0,%1,%2,%3}, {%4,%5,%6,%7}, {%8,%9}, {%0,%1,%2,%3};"
        : "+f"(c[0]), "+f"(c[1]), "+f"(c[2]), "+f"(c[3])
        : "r"(a[0]), "r"(a[1]), "r"(a[2]), "r"(a[3]), "r"(b[0]), "r"(b[1]));
}
__device__ __forceinline__ void ldsm4(uint32_t r[4], uint32_t addr) {
    asm volatile("ldmatrix.sync.aligned.m8n8.x4.shared.b16 {%0,%1,%2,%3}, [%4];"
                 : "=r"(r[0]), "=r"(r[1]), "=r"(r[2]), "=r"(r[3]) : "r"(addr));
}
__device__ __forceinline__ uint32_t smem_to_u32(const void* p) {
    uint32_t a;
    asm("{ .reg .u64 t; cvta.to.shared.u64 t, %1; cvt.u32.u64 %0, t; }" : "=r"(a) : "l"(p));
    return a;
}

// split a float2 into packed bf16x2 hi and lo (residual) parts.
__device__ __forceinline__ void split2(float2 v, uint32_t& hi, uint32_t& lo) {
    uint32_t h;
    asm("cvt.rn.bf16x2.f32 %0, %1, %2;" : "=r"(h) : "f"(v.y), "f"(v.x));
    float h0 = __uint_as_float(h << 16);
    float h1 = __uint_as_float(h & 0xFFFF0000u);
    float l0 = v.x - h0, l1 = v.y - h1;
    asm("cvt.rn.bf16x2.f32 %0, %1, %2;" : "=r"(lo) : "f"(l1), "f"(l0));
    hi = h;
}

// ldmatrix.x4 A-fragment load from a bf16 plane (row-major, SAH halves/row).
// matrix0: rows m0..+7 k..+7, m1: rows+8, m2: k+8, m3: rows+8,k+8.
__device__ __forceinline__ void ldAm(uint32_t r[4], uint32_t plane, int SAH,
                                     int row0, int kabs, int lane) {
    int j = lane >> 3, rr = lane & 7;
    int row = row0 + ((j & 1) << 3) + rr;
    int col = kabs + ((j >> 1) << 3);
    ldsm4(r, plane + (uint32_t)(row * SAH + col) * 2);
}

// One k16 step of warp GEMM on bf16 planes: 32 rows x (NTILES*16) cols, 3-term split.
template <int NTILES>
__device__ __forceinline__ void gemm_kstep_p(uint32_t aHi, uint32_t aLo, int SAH, int m0,
                                             uint32_t whi, uint32_t wlo, int SWB,
                                             int n0loc, int k0loc, int kabs, int lane,
                                             float acc[2][NTILES * 2][4]) {
    uint32_t ahi[2][4], alo[2][4];
    ldAm(ahi[0], aHi, SAH, m0,      kabs, lane);
    ldAm(ahi[1], aHi, SAH, m0 + 16, kabs, lane);
    ldAm(alo[0], aLo, SAH, m0,      kabs, lane);
    ldAm(alo[1], aLo, SAH, m0 + 16, kabs, lane);
    uint32_t bh[NTILES][4], bl[NTILES][4];
    const int nl = n0loc + (lane & 7) + ((lane >> 4) << 3);
    const int kk = k0loc + (((lane >> 3) & 1) << 3);
#pragma unroll
    for (int nt = 0; nt < NTILES; nt++) {
        uint32_t off = (uint32_t)((nl + nt * 16) * SWB + kk) * 2;
        ldsm4(bh[nt], whi + off);
        ldsm4(bl[nt], wlo + off);
    }
#pragma unroll
    for (int mi = 0; mi < 2; mi++)
#pragma unroll
        for (int nt = 0; nt < NTILES; nt++) {
            mma16816(acc[mi][2 * nt],     ahi[mi], &bh[nt][0]);
            mma16816(acc[mi][2 * nt + 1], ahi[mi], &bh[nt][2]);
        }
#pragma unroll
    for (int mi = 0; mi < 2; mi++)
#pragma unroll
        for (int nt = 0; nt < NTILES; nt++) {
            mma16816(acc[mi][2 * nt],     ahi[mi], &bl[nt][0]);
            mma16816(acc[mi][2 * nt + 1], ahi[mi], &bl[nt][2]);
        }
#pragma unroll
    for (int mi = 0; mi < 2; mi++)
#pragma unroll
        for (int nt = 0; nt < NTILES; nt++) {
            mma16816(acc[mi][2 * nt],     alo[mi], &bh[nt][0]);
            mma16816(acc[mi][2 * nt + 1], alo[mi], &bh[nt][2]);
        }
}

// Weight slab staging: global fp32 -> smem bf16 hi/lo planes, row stride KF+8 halves.
template <int C, int KF>
__device__ __forceinline__ void ldgS(float2 rw[8], const float* __restrict__ W,
                                     int ldW, int cbase, int kbase) {
    static_assert(C * KF == 16 * NT, "slab size");
    constexpr int KF2 = KF / 2;
#pragma unroll
    for (int j = 0; j < 8; j++) {
        int idx = threadIdx.x + j * NT;
        int c = idx / KF2, k2 = idx % KF2;
        rw[j] = *(const float2*)(W + (size_t)(cbase + c) * ldW + kbase + 2 * k2);
    }
}
template <int C, int KF>
__device__ __forceinline__ void stsS(uint32_t* __restrict__ whi32,
                                     uint32_t* __restrict__ wlo32, const float2 rw[8]) {
    constexpr int KF2 = KF / 2;
    constexpr int SWB32 = (KF + 8) / 2;
#pragma unroll
    for (int j = 0; j < 8; j++) {
        int idx = threadIdx.x + j * NT;
        int c = idx / KF2, k2 = idx % KF2;
        uint32_t hi, lo;
        split2(rw[j], hi, lo);
        whi32[c * SWB32 + k2] = hi;
        wlo32[c * SWB32 + k2] = lo;
    }
}
// double-size slab (32 floats/thread) for k_front block4
template <int C, int KF>
__device__ __forceinline__ void ldgS2(float2 rw[16], const float* __restrict__ W,
                                      int ldW, int cbase, int kbase) {
    static_assert(C * KF == 32 * NT, "slab size");
    constexpr int KF2 = KF / 2;
#pragma unroll
    for (int j = 0; j < 16; j++) {
        int idx = threadIdx.x + j * NT;
        int c = idx / KF2, k2 = idx % KF2;
        rw[j] = *(const float2*)(W + (size_t)(cbase + c) * ldW + kbase + 2 * k2);
    }
}
template <int C, int KF>
__device__ __forceinline__ void stsS2(uint32_t* __restrict__ whi32,
                                      uint32_t* __restrict__ wlo32, const float2 rw[16]) {
    constexpr int KF2 = KF / 2;
    constexpr int SWB32 = (KF + 8) / 2;
#pragma unroll
    for (int j = 0; j < 16; j++) {
        int idx = threadIdx.x + j * NT;
        int c = idx / KF2, k2 = idx % KF2;
        uint32_t hi, lo;
        split2(rw[j], hi, lo);
        whi32[c * SWB32 + k2] = hi;
        wlo32[c * SWB32 + k2] = lo;
    }
}

// Epilogue: relu(acc + bias) -> bf16 hi/lo planes (u32-addressed, SRU u32/row).
template <int NJ>
__device__ __forceinline__ void epi_store_p(uint32_t* __restrict__ hiP,
                                            uint32_t* __restrict__ loP, int SRU,
                                            int m0, int nbase, const float* __restrict__ bias,
                                            float acc[2][NJ][4], int lane) {
    int g = lane >> 2, t = lane & 3;
#pragma unroll
    for (int mi = 0; mi < 2; mi++)
#pragma unroll
        for (int nj = 0; nj < NJ; nj++) {
            int col = nbase + nj * 8 + 2 * t;
            float2 b = __ldg((const float2*)(bias + col));
            int row = m0 + mi * 16 + g;
            uint32_t h0, l0, h1, l1;
            split2(make_float2(frelu(acc[mi][nj][0] + b.x), frelu(acc[mi][nj][1] + b.y)), h0, l0);
            split2(make_float2(frelu(acc[mi][nj][2] + b.x), frelu(acc[mi][nj][3] + b.y)), h1, l1);
            int cp = col >> 1;
            hiP[row * SRU + cp] = h0;       loP[row * SRU + cp] = l0;
            hiP[(row + 8) * SRU + cp] = h1; loP[(row + 8) * SRU + cp] = l1;
        }
}
// Epilogue: relu(acc + bias) -> fp32 smem (for block7 -> block8)
template <int NJ>
__device__ __forceinline__ void epi_store(float* __restrict__ Z, int SZ, int m0, int nbase,
                                          const float* __restrict__ bias,
                                          float acc[2][NJ][4], int lane) {
    int g = lane >> 2, t = lane & 3;
#pragma unroll
    for (int mi = 0; mi < 2; mi++)
#pragma unroll
        for (int nj = 0; nj < NJ; nj++) {
            int col = nbase + nj * 8 + 2 * t;
            float2 b = __ldg((const float2*)(bias + col));
            int row = m0 + mi * 16 + g;
            *(float2*)(Z + (size_t)row * SZ + col) =
                make_float2(frelu(acc[mi][nj][0] + b.x), frelu(acc[mi][nj][1] + b.y));
            *(float2*)(Z + (size_t)(row + 8) * SZ + col) =
                make_float2(frelu(acc[mi][nj][2] + b.x), frelu(acc[mi][nj][3] + b.y));
        }
}

// ---- small-tile SIMT path (blocks 1-3) ----
template <int KS, int CW>
__device__ __forceinline__ void ldgW16(float r[16], const float* __restrict__ W,
                                       int ldW, int cbase, int kbase) {
#pragma unroll
    for (int j = 0; j < 16; j++) {
        int idx = threadIdx.x + j * NT;
        int c = idx / KS, k = idx % KS;
        r[j] = __ldg(W + (cbase + c) * ldW + (kbase + k));
    }
}
template <int KS, int CW>
__device__ __forceinline__ void stsW16(float* __restrict__ Wb, const float r[16]) {
#pragma unroll
    for (int j = 0; j < 16; j++) {
        int idx = threadIdx.x + j * NT;
        int c = idx / KS, k = idx % KS;
        Wb[k * (CW + 4) + c] = r[j];
    }
}
template <int TP, int PGR, int CW, int KS>
__device__ __forceinline__ void mma2(const float* __restrict__ A, int SA,
                                     const float* __restrict__ Wb,
                                     int pgrp, int cgrp, u64 acc[TP][4]) {
    constexpr int SWB = CW + 4;
    const float* Ap[TP];
#pragma unroll
    for (int i = 0; i < TP; i++) Ap[i] = A + (pgrp + i * PGR) * SA;
    const char* wbase = (const char*)(Wb + cgrp * 8);
#pragma unroll 8
    for (int k = 0; k < KS; k++) {
        ulonglong2 u0 = *(const ulonglong2*)(wbase + (size_t)k * (SWB * 4));
        ulonglong2 u1 = *(const ulonglong2*)(wbase + (size_t)k * (SWB * 4) + 16);
#pragma unroll
        for (int i = 0; i < TP; i++) {
            u64 a2 = splat2(Ap[i][k]);
            acc[i][0] = fma2(a2, u0.x, acc[i][0]);
            acc[i][1] = fma2(a2, u0.y, acc[i][1]);
            acc[i][2] = fma2(a2, u1.x, acc[i][2]);
            acc[i][3] = fma2(a2, u1.y, acc[i][3]);
        }
    }
}

// -------- init: reset max-pool accumulator each replay --------
__global__ void k_init() {
    g_gmax[threadIdx.x] = 0;
}

// ============================================================
// Kernel A: blocks 1..3 SIMT + block4 via HMMA on bf16 planes.
// CTA = 128 points, 256 threads.
// smem floats:
//   a1 fp32 [128][132] @0 (16896); aHi/aLo planes overlay @0/@8704 (u32, 8704 each)
//   hbuf [128][68] @17408 (8704)
//   Wb SIMT @26112 (4352)
//   wslab planes @30464 (9216: 4608 u32 per plane)
//   gmax @39680 (1024)
//   consts @40704 (832)
// ============================================================
#define SMEM1_FLOATS 41536

__global__ __launch_bounds__(NT, 1) void k_front(
    const float* __restrict__ x,
    const float* __restrict__ W1, const float* __restrict__ b1,
    const float* __restrict__ W2, const float* __restrict__ b2,
    const float* __restrict__ W3, const float* __restrict__ b3,
    const float* __restrict__ W4, const float* __restrict__ b4) {
    extern __shared__ float sm[];
    float* a1 = sm;                         // stride 132
    uint32_t* aHi = (uint32_t*)sm;          // 8704 u32, SAH=136 halves (SRU=68)
    uint32_t* aLo = aHi + 8704;
    float* hbuf = sm + 17408;
    float* Wb   = sm + 26112;
    uint32_t* whi32 = (uint32_t*)(sm + 30464);  // 4608 u32 (SWB=72 halves)
    uint32_t* wlo32 = whi32 + 4608;
    int*   gmax = (int*)(sm + 39680);
    float* cst  = sm + 40704;
    float* w1s = cst;          // 192
    float* b1s = cst + 192;    // 64
    float* xs  = cst + 256;    // 384
    float* b2s = cst + 640;    // 64
    float* b3s = cst + 704;    // 128

    const int tid   = threadIdx.x;
    const int wid   = tid >> 5;
    const int lane  = tid & 31;
    const int pbase = blockIdx.x * 128;

    for (int i = tid; i < 1024; i += NT) gmax[i] = 0;
    for (int i = tid; i < 192; i += NT) w1s[i] = W1[i];
    for (int i = tid; i < 64; i += NT) { b1s[i] = b1[i]; b2s[i] = b2[i]; }
    for (int i = tid; i < 128; i += NT) b3s[i] = b3[i];
    for (int i = tid; i < 384; i += NT) xs[i] = x[pbase * 3 + i];

    float rw[16];
    ldgW16<64, 64>(rw, W2, 64, 0, 0);     // prefetch W2 slab
    __syncthreads();

    // ---- block1: a1 = relu(x @ W1^T + b1)
    for (int idx = tid; idx < 128 * 64; idx += NT) {
        int p = idx >> 6, c = idx & 63;
        float v = fmaf(xs[p * 3 + 2], w1s[c * 3 + 2],
                  fmaf(xs[p * 3 + 1], w1s[c * 3 + 1],
                  fmaf(xs[p * 3 + 0], w1s[c * 3 + 0], b1s[c])));
        a1[p * 132 + c] = frelu(v);
    }
    __syncthreads();

    stsW16<64, 64>(Wb, rw);
    ldgW16<64, 64>(rw, W3, 64, 0, 0);
    __syncthreads();

    const int opg = tid >> 3;  // 0..31
    const int ocg = tid & 7;   // 0..7
    const int oc0 = ocg * 8;

    // ---- block2: h = relu(a1 @ W2^T + b2) -> hbuf (+ g_h)
    {
        u64 acc[4][4];
#pragma unroll
        for (int i = 0; i < 4; i++)
#pragma unroll
            for (int j = 0; j < 4; j++) acc[i][j] = pack2(b2s[oc0 + 2 * j], b2s[oc0 + 2 * j + 1]);
        mma2<4, 32, 64, 64>(a1, 132, Wb, opg, ocg, acc);
#pragma unroll
        for (int i = 0; i < 4; i++)
#pragma unroll
            for (int j = 0; j < 4; j++) {
                float2 f = unpack2(acc[i][j]);
                hbuf[(opg + i * 32) * 68 + oc0 + 2 * j]     = frelu(f.x);
                hbuf[(opg + i * 32) * 68 + oc0 + 2 * j + 1] = frelu(f.y);
            }
    }
    __syncthreads();

    stsW16<64, 64>(Wb, rw);
    ldgW16<64, 64>(rw, W3, 64, 64, 0);
    __syncthreads();

    for (int idx = tid; idx < 128 * 64; idx += NT) {
        int p = idx >> 6, c = idx & 63;
        g_h[(pbase + p) * 64 + c] = hbuf[p * 68 + c];
    }

    // ---- block3 chunk 0 -> a-planes cols 0..63 (overlays dead a1)
    {
        u64 acc[4][4];
#pragma unroll
        for (int i = 0; i < 4; i++)
#pragma unroll
            for (int j = 0; j < 4; j++) acc[i][j] = pack2(b3s[oc0 + 2 * j], b3s[oc0 + 2 * j + 1]);
        mma2<4, 32, 64, 64>(hbuf, 68, Wb, opg, ocg, acc);
#pragma unroll
        for (int i = 0; i < 4; i++)
#pragma unroll
            for (int j = 0; j < 4; j++) {
                float2 f = unpack2(acc[i][j]);
                uint32_t hi, lo;
                split2(make_float2(frelu(f.x), frelu(f.y)), hi, lo);
                int row = opg + i * 32, cp = (oc0 >> 1) + j;
                aHi[row * 68 + cp] = hi;
                aLo[row * 68 + cp] = lo;
            }
    }
    __syncthreads();

    stsW16<64, 64>(Wb, rw);
    float2 rw2[16];
    ldgS2<128, 64>(rw2, W4, 128, 0, 0);   // prefetch W4 slab(chunk0, k0)
    __syncthreads();

    // ---- block3 chunk 1 -> a-planes cols 64..127
    {
        u64 acc[4][4];
#pragma unroll
        for (int i = 0; i < 4; i++)
#pragma unroll
            for (int j = 0; j < 4; j++) acc[i][j] = pack2(b3s[64 + oc0 + 2 * j], b3s[64 + oc0 + 2 * j + 1]);
        mma2<4, 32, 64, 64>(hbuf, 68, Wb, opg, ocg, acc);
#pragma unroll
        for (int i = 0; i < 4; i++)
#pragma unroll
            for (int j = 0; j < 4; j++) {
                float2 f = unpack2(acc[i][j]);
                uint32_t hi, lo;
                split2(make_float2(frelu(f.x), frelu(f.y)), hi, lo);
                int row = opg + i * 32, cp = 32 + (oc0 >> 1) + j;
                aHi[row * 68 + cp] = hi;
                aLo[row * 68 + cp] = lo;
            }
    }

    // ---- block4: 8 chunks of 128 out-ch via HMMA on planes; only max kept.
    const uint32_t aHi_a = smem_to_u32(aHi);
    const uint32_t aLo_a = smem_to_u32(aLo);
    const uint32_t whi_a = smem_to_u32(whi32);
    const uint32_t wlo_a = smem_to_u32(wlo32);
    const int m0 = (wid & 3) * 32;   // 4 M-warps
    const int n0 = (wid >> 2) * 64;  // 2 N-warps

    for (int cc = 0; cc < 8; cc++) {
        float acc[2][8][4];
#pragma unroll
        for (int mi = 0; mi < 2; mi++)
#pragma unroll
            for (int nj = 0; nj < 8; nj++)
#pragma unroll
                for (int q = 0; q < 4; q++) acc[mi][nj][q] = 0.f;

        for (int s = 0; s < 2; s++) {
            __syncthreads();
            stsS2<128, 64>(whi32, wlo32, rw2);
            int t = cc * 2 + s + 1;
            if (t < 16) ldgS2<128, 64>(rw2, W4, 128, (t >> 1) * 128, (t & 1) * 64);
            __syncthreads();
#pragma unroll
            for (int q = 0; q < 4; q++)
                gemm_kstep_p<4>(aHi_a, aLo_a, 136, m0, whi_a, wlo_a, 72,
                                n0, q * 16, s * 64 + q * 16, lane, acc);
        }

        // epilogue: in-thread max over rows, shfl over groups, bias+relu, atomicMax
        float m0v[8], m1v[8];
#pragma unroll
        for (int nj = 0; nj < 8; nj++) {
            m0v[nj] = fmaxf(fmaxf(acc[0][nj][0], acc[0][nj][2]),
                            fmaxf(acc[1][nj][0], acc[1][nj][2]));
            m1v[nj] = fmaxf(fmaxf(acc[0][nj][1], acc[0][nj][3]),
                            fmaxf(acc[1][nj][1], acc[1][nj][3]));
        }
#pragma unroll
        for (int m = 4; m < 32; m <<= 1)
#pragma unroll
            for (int nj = 0; nj < 8; nj++) {
                m0v[nj] = fmaxf(m0v[nj], __shfl_xor_sync(0xffffffffu, m0v[nj], m));
                m1v[nj] = fmaxf(m1v[nj], __shfl_xor_sync(0xffffffffu, m1v[nj], m));
            }
        if ((lane >> 2) == 0) {
            int t = lane & 3;
#pragma unroll
            for (int nj = 0; nj < 8; nj++) {
                int col = cc * 128 + n0 + nj * 8 + 2 * t;
                float2 b = __ldg((const float2*)(b4 + col));
                atomicMax(&gmax[col],     __float_as_int(frelu(m0v[nj] + b.x)));
                atomicMax(&gmax[col + 1], __float_as_int(frelu(m1v[nj] + b.y)));
            }
        }
    }
    __syncthreads();
    for (int i = tid; i < 1024; i += NT) atomicMax(&g_gmax[i], gmax[i]);
}

// ============================================================
// Kernel B: c5[j] = b5[j] + sum_i W5[j][64+i] * g[i]
// ============================================================
__global__ void k_c5(const float* __restrict__ W5, const float* __restrict__ b5) {
    __shared__ float gs[1024];
    const int tid = threadIdx.x;
    for (int i = tid; i < 1024; i += 256) gs[i] = __int_as_float(g_gmax[i]);
    __syncthreads();
    const int j = blockIdx.x * 64 + (tid >> 2);
    const int q = tid & 3;
    const float* wr = W5 + j * 1088 + 64 + q * 256;
    const float* gr = gs + q * 256;
    float s = 0.f;
#pragma unroll 8
    for (int i = 0; i < 256; i++) s = fmaf(wr[i], gr[i], s);
    s += __shfl_xor_sync(0xffffffffu, s, 1);
    s += __shfl_xor_sync(0xffffffffu, s, 2);
    if (q == 0) g_c5[j] = s + b5[j];
}

// ============================================================
// Kernel C: blocks 5..8 via HMMA on bf16 planes. CTA = 64 pts, 256 thr.
// smem floats:
//   z5 planes @0      (33280: 16640 u32 x2, SAH=520, SRU=260)  (z7 fp32 overlays)
//   z6 planes @33280  (16896: 8448 u32 x2,  SAH=264, SRU=132)  (h planes overlay)
//   wslab planes @50176 (6144: 3072 u32 x2 max)
// ============================================================
#define SMEM3_FLOATS 56320

__global__ __launch_bounds__(NT, 1) void k_back(
    const float* __restrict__ W5,
    const float* __restrict__ W6, const float* __restrict__ b6,
    const float* __restrict__ W7, const float* __restrict__ b7,
    const float* __restrict__ W8, const float* __restrict__ b8,
    float* __restrict__ out) {
    extern __shared__ float sm[];
    uint32_t* z5Hi = (uint32_t*)sm;           // 16640 u32
    uint32_t* z5Lo = z5Hi + 16640;
    uint32_t* z6Hi = (uint32_t*)(sm + 33280); // 8448 u32
    uint32_t* z6Lo = z6Hi + 8448;
    uint32_t* hHi  = z6Hi;                    // overlay: 2304 u32, SAH=72 (SRU=36)
    uint32_t* hLo  = hHi + 2304;
    uint32_t* whi32 = (uint32_t*)(sm + 50176); // 3072 u32 max
    uint32_t* wlo32 = whi32 + 3072;
    float* z7 = sm;                           // stride 132 (overlays z5 planes)

    const int tid   = threadIdx.x;
    const int wid   = tid >> 5;
    const int lane  = tid & 31;
    const int pbase = blockIdx.x * 64;

    // load h -> bf16 planes
    for (int idx = tid; idx < 64 * 32; idx += NT) {
        int p = idx >> 5, c2 = idx & 31;
        float2 v = *(const float2*)(g_h + (size_t)(pbase + p) * 64 + 2 * c2);
        uint32_t hi, lo;
        split2(v, hi, lo);
        hHi[p * 36 + c2] = hi;
        hLo[p * 36 + c2] = lo;
    }

    float2 rw2[8];
    ldgS<256, 16>(rw2, W5, 1088, 0, 0);   // W5a pass0 slab0
    __syncthreads();

    const uint32_t z5Hi_a = smem_to_u32(z5Hi);
    const uint32_t z5Lo_a = smem_to_u32(z5Lo);
    const uint32_t z6Hi_a = smem_to_u32(z6Hi);
    const uint32_t z6Lo_a = smem_to_u32(z6Lo);
    const uint32_t hHi_a  = smem_to_u32(hHi);
    const uint32_t hLo_a  = smem_to_u32(hLo);
    const uint32_t whi_a  = smem_to_u32(whi32);
    const uint32_t wlo_a  = smem_to_u32(wlo32);
    const int m0 = (wid & 1) * 32;   // 2 M-warps
    const int wn = wid >> 1;         // 4 N-warps

    // ---- block5: z5 = relu(h @ W5a^T + c5). 2 N-passes of 256, K=64.
    for (int cc = 0; cc < 2; cc++) {
        float acc[2][8][4];
#pragma unroll
        for (int mi = 0; mi < 2; mi++)
#pragma unroll
            for (int nj = 0; nj < 8; nj++)
#pragma unroll
                for (int q = 0; q < 4; q++) acc[mi][nj][q] = 0.f;
        for (int s = 0; s < 4; s++) {
            __syncthreads();
            stsS<256, 16>(whi32, wlo32, rw2);
            int t = cc * 4 + s + 1;
            if (t < 8)       ldgS<256, 16>(rw2, W5, 1088, (t >> 2) * 256, (t & 3) * 16);
            else if (t == 8) ldgS<256, 16>(rw2, W6, 512, 0, 0);
            __syncthreads();
            gemm_kstep_p<4>(hHi_a, hLo_a, 72, m0, whi_a, wlo_a, 24,
                            wn * 64, 0, s * 16, lane, acc);
        }
        epi_store_p<8>(z5Hi, z5Lo, 260, m0, cc * 256 + wn * 64, g_c5, acc, lane);
    }

    // ---- block6: z6 = relu(z5 @ W6^T + b6). N=256, K=512.
    {
        float acc[2][8][4];
#pragma unroll
        for (int mi = 0; mi < 2; mi++)
#pragma unroll
            for (int nj = 0; nj < 8; nj++)
#pragma unroll
                for (int q = 0; q < 4; q++) acc[mi][nj][q] = 0.f;
        for (int s = 0; s < 32; s++) {
            __syncthreads();
            stsS<256, 16>(whi32, wlo32, rw2);
            int t = s + 1;
            if (t < 32) ldgS<256, 16>(rw2, W6, 512, 0, t * 16);
            else        ldgS<128, 32>(rw2, W7, 256, 0, 0);
            __syncthreads();
            gemm_kstep_p<4>(z5Hi_a, z5Lo_a, 520, m0, whi_a, wlo_a, 24,
                            wn * 64, 0, s * 16, lane, acc);
        }
        epi_store_p<8>(z6Hi, z6Lo, 132, m0, wn * 64, b6, acc, lane);
    }

    // ---- block7: z7 = relu(z6 @ W7^T + b7). N=128, K=256. fp32 out over z5.
    {
        float acc[2][4][4];
#pragma unroll
        for (int mi = 0; mi < 2; mi++)
#pragma unroll
            for (int nj = 0; nj < 4; nj++)
#pragma unroll
                for (int q = 0; q < 4; q++) acc[mi][nj][q] = 0.f;
        for (int s = 0; s < 8; s++) {
            __syncthreads();
            stsS<128, 32>(whi32, wlo32, rw2);
            if (s < 7) ldgS<128, 32>(rw2, W7, 256, 0, (s + 1) * 32);
            __syncthreads();
            gemm_kstep_p<2>(z6Hi_a, z6Lo_a, 264, m0, whi_a, wlo_a, 40,
                            wn * 32, 0,  s * 32,      lane, acc);
            gemm_kstep_p<2>(z6Hi_a, z6Lo_a, 264, m0, whi_a, wlo_a, 40,
                            wn * 32, 16, s * 32 + 16, lane, acc);
        }
        __syncthreads();   // z5 planes dead; safe to overlay z7 fp32
        epi_store<4>(z7, 132, m0, wn * 32, b7, acc, lane);
    }
    __syncthreads();

    // ---- block8: out = z7 @ W8^T + b8 (no relu)
    if (tid < 64) {
        const float* zr = z7 + tid * 132;
        float s = __ldg(b8);
#pragma unroll 8
        for (int k = 0; k < 128; k++) s = fmaf(zr[k], __ldg(W8 + k), s);
        out[pbase + tid] = s;
    }
}

// ============================================================
extern "C" void kernel_launch(void* const* d_in, const int* in_sizes, int n_in,
                              void* d_out, int out_size) {
    const float* x  = (const float*)d_in[0];
    const float* W1 = (const float*)d_in[1];  const float* b1 = (const float*)d_in[2];
    const float* W2 = (const float*)d_in[3];  const float* b2 = (const float*)d_in[4];
    const float* W3 = (const float*)d_in[5];  const float* b3 = (const float*)d_in[6];
    const float* W4 = (const float*)d_in[7];  const float* b4 = (const float*)d_in[8];
    const float* W5 = (const float*)d_in[9];  const float* b5 = (const float*)d_in[10];
    const float* W6 = (const float*)d_in[11]; const float* b6 = (const float*)d_in[12];
    const float* W7 = (const float*)d_in[13]; const float* b7 = (const float*)d_in[14];
    const float* W8 = (const float*)d_in[15]; const float* b8 = (const float*)d_in[16];
    float* out = (float*)d_out;

    const int n = in_sizes[0] / 3;  // 65536

    const int smem1 = SMEM1_FLOATS * (int)sizeof(float);
    const int smem3 = SMEM3_FLOATS * (int)sizeof(float);
    cudaFuncSetAttribute(k_front, cudaFuncAttributeMaxDynamicSharedMemorySize, smem1);
    cudaFuncSetAttribute(k_back,  cudaFuncAttributeMaxDynamicSharedMemorySize, smem3);

    k_init<<<1, 1024>>>();
    k_front<<<n / 128, NT, smem1>>>(x, W1, b1, W2, b2, W3, b3, W4, b4);
    k_c5<<<8, 256>>>(W5, b5);
    k_back<<<n / 64, NT, smem3>>>(W5, W6, b6, W7, b7, W8, b8, out);
}

// round 9
// speedup vs baseline: 3.1310x; 1.1178x over previous
#include <cuda_runtime.h>
#include <cuda_bf16.h>
#include <cstdint>

#define NT 256

typedef unsigned long long u64;

// -------- persistent device scratch (no allocs allowed) --------
__device__ float g_h[65536 * 64];   // h = block2 output, needed for skip-concat
__device__ int   g_gmax[1024];      // global max-pool accumulator (float bits, >=0)
__device__ float g_c5[512];         // c5 = b5 + W5[:,64:] @ g

// pre-split bf16 weight planes, stored as exact smem slab images (hi plane || lo plane)
__device__ __align__(16) uint32_t g_w4[16 * 9216];  // block4: 16 slabs [128][36u32] x2
__device__ __align__(16) uint32_t g_w5[8 * 6144];   // block5: 8 slabs [256][12u32] x2
__device__ __align__(16) uint32_t g_w6[32 * 6144];  // block6: 32 slabs [256][12u32] x2
__device__ __align__(16) uint32_t g_w7[8 * 5120];   // block7: 8 slabs [128][20u32] x2

__device__ __forceinline__ float frelu(float v) { return v > 0.f ? v : 0.f; }

// ---- packed f32x2 helpers (FFMA2, for the small SIMT blocks) ----
__device__ __forceinline__ u64 fma2(u64 a, u64 b, u64 c) {
    u64 d; asm("fma.rn.f32x2 %0, %1, %2, %3;" : "=l"(d) : "l"(a), "l"(b), "l"(c)); return d;
}
__device__ __forceinline__ u64 splat2(float a) {
    u64 d; asm("mov.b64 %0, {%1, %1};" : "=l"(d) : "f"(a)); return d;
}
__device__ __forceinline__ u64 pack2(float lo, float hi) {
    u64 d; asm("mov.b64 %0, {%1, %2};" : "=l"(d) : "f"(lo), "f"(hi)); return d;
}
__device__ __forceinline__ float2 unpack2(u64 v) {
    float2 f; asm("mov.b64 {%0, %1}, %2;" : "=f"(f.x), "=f"(f.y) : "l"(v)); return f;
}

// ============================================================
// HMMA (mma.sync) machinery — compiles at plain sm_103 target.
// ============================================================
__device__ __forceinline__ void mma16816(float* c, const uint32_t* a, const uint32_t* b) {
    asm volatile(
        "mma.sync.aligned.m16n8k16.row.col.f32.bf16.bf16.f32 "
        "{%0,%1,%2,%3}, {%4,%5,%6,%7}, {%8,%9}, {%0,%1,%2,%3};"
        : "+f"(c[0]), "+f"(c[1]), "+f"(c[2]), "+f"(c[3])
        : "r"(a[0]), "r"(a[1]), "r"(a[2]), "r"(a[3]), "r"(b[0]), "r"(b[1]));
}
__device__ __forceinline__ void ldsm4(uint32_t r[4], uint32_t addr) {
    asm volatile("ldmatrix.sync.aligned.m8n8.x4.shared.b16 {%0,%1,%2,%3}, [%4];"
                 : "=r"(r[0]), "=r"(r[1]), "=r"(r[2]), "=r"(r[3]) : "r"(addr));
}
__device__ __forceinline__ uint32_t smem_to_u32(const void* p) {
    uint32_t a;
    asm("{ .reg .u64 t; cvta.to.shared.u64 t, %1; cvt.u32.u64 %0, t; }" : "=r"(a) : "l"(p));
    return a;
}

// split a float2 into packed bf16x2 hi and lo (residual) parts.
__device__ __forceinline__ void split2(float2 v, uint32_t& hi, uint32_t& lo) {
    uint32_t h;
    asm("cvt.rn.bf16x2.f32 %0, %1, %2;" : "=r"(h) : "f"(v.y), "f"(v.x));
    float h0 = __uint_as_float(h << 16);
    float h1 = __uint_as_float(h & 0xFFFF0000u);
    float l0 = v.x - h0, l1 = v.y - h1;
    asm("cvt.rn.bf16x2.f32 %0, %1, %2;" : "=r"(lo) : "f"(l1), "f"(l0));
    hi = h;
}

// ldmatrix.x4 A-fragment load from a bf16 plane (row-major, SAH halves/row).
__device__ __forceinline__ void ldAm(uint32_t r[4], uint32_t plane, int SAH,
                                     int row0, int kabs, int lane) {
    int j = lane >> 3, rr = lane & 7;
    int row = row0 + ((j & 1) << 3) + rr;
    int col = kabs + ((j >> 1) << 3);
    ldsm4(r, plane + (uint32_t)(row * SAH + col) * 2);
}

// One k16 step of warp GEMM on bf16 planes: 32 rows x (NTILES*16) cols, 3-term split.
template <int NTILES>
__device__ __forceinline__ void gemm_kstep_p(uint32_t aHi, uint32_t aLo, int SAH, int m0,
                                             uint32_t whi, uint32_t wlo, int SWB,
                                             int n0loc, int k0loc, int kabs, int lane,
                                             float acc[2][NTILES * 2][4]) {
    uint32_t ahi[2][4], alo[2][4];
    ldAm(ahi[0], aHi, SAH, m0,      kabs, lane);
    ldAm(ahi[1], aHi, SAH, m0 + 16, kabs, lane);
    ldAm(alo[0], aLo, SAH, m0,      kabs, lane);
    ldAm(alo[1], aLo, SAH, m0 + 16, kabs, lane);
    uint32_t bh[NTILES][4], bl[NTILES][4];
    const int nl = n0loc + (lane & 7) + ((lane >> 4) << 3);
    const int kk = k0loc + (((lane >> 3) & 1) << 3);
#pragma unroll
    for (int nt = 0; nt < NTILES; nt++) {
        uint32_t off = (uint32_t)((nl + nt * 16) * SWB + kk) * 2;
        ldsm4(bh[nt], whi + off);
        ldsm4(bl[nt], wlo + off);
    }
#pragma unroll
    for (int mi = 0; mi < 2; mi++)
#pragma unroll
        for (int nt = 0; nt < NTILES; nt++) {
            mma16816(acc[mi][2 * nt],     ahi[mi], &bh[nt][0]);
            mma16816(acc[mi][2 * nt + 1], ahi[mi], &bh[nt][2]);
        }
#pragma unroll
    for (int mi = 0; mi < 2; mi++)
#pragma unroll
        for (int nt = 0; nt < NTILES; nt++) {
            mma16816(acc[mi][2 * nt],     ahi[mi], &bl[nt][0]);
            mma16816(acc[mi][2 * nt + 1], ahi[mi], &bl[nt][2]);
        }
#pragma unroll
    for (int mi = 0; mi < 2; mi++)
#pragma unroll
        for (int nt = 0; nt < NTILES; nt++) {
            mma16816(acc[mi][2 * nt],     alo[mi], &bh[nt][0]);
            mma16816(acc[mi][2 * nt + 1], alo[mi], &bh[nt][2]);
        }
}

// ---- slab staging: pure uint4 copy from pre-split global images ----
template <int NV>
__device__ __forceinline__ void ldgP(uint4 r[NV], const uint32_t* __restrict__ src) {
#pragma unroll
    for (int j = 0; j < NV; j++)
        r[j] = ((const uint4*)src)[threadIdx.x + j * NT];
}
template <int NV>
__device__ __forceinline__ void stsP(uint32_t* __restrict__ dst, const uint4 r[NV]) {
#pragma unroll
    for (int j = 0; j < NV; j++)
        ((uint4*)dst)[threadIdx.x + j * NT] = r[j];
}

// Epilogue: relu(acc + bias) -> bf16 hi/lo planes (u32-addressed, SRU u32/row).
template <int NJ>
__device__ __forceinline__ void epi_store_p(uint32_t* __restrict__ hiP,
                                            uint32_t* __restrict__ loP, int SRU,
                                            int m0, int nbase, const float* __restrict__ bias,
                                            float acc[2][NJ][4], int lane) {
    int g = lane >> 2, t = lane & 3;
#pragma unroll
    for (int mi = 0; mi < 2; mi++)
#pragma unroll
        for (int nj = 0; nj < NJ; nj++) {
            int col = nbase + nj * 8 + 2 * t;
            float2 b = __ldg((const float2*)(bias + col));
            int row = m0 + mi * 16 + g;
            uint32_t h0, l0, h1, l1;
            split2(make_float2(frelu(acc[mi][nj][0] + b.x), frelu(acc[mi][nj][1] + b.y)), h0, l0);
            split2(make_float2(frelu(acc[mi][nj][2] + b.x), frelu(acc[mi][nj][3] + b.y)), h1, l1);
            int cp = col >> 1;
            hiP[row * SRU + cp] = h0;       loP[row * SRU + cp] = l0;
            hiP[(row + 8) * SRU + cp] = h1; loP[(row + 8) * SRU + cp] = l1;
        }
}
// Epilogue: relu(acc + bias) -> fp32 smem (for block7 -> block8)
template <int NJ>
__device__ __forceinline__ void epi_store(float* __restrict__ Z, int SZ, int m0, int nbase,
                                          const float* __restrict__ bias,
                                          float acc[2][NJ][4], int lane) {
    int g = lane >> 2, t = lane & 3;
#pragma unroll
    for (int mi = 0; mi < 2; mi++)
#pragma unroll
        for (int nj = 0; nj < NJ; nj++) {
            int col = nbase + nj * 8 + 2 * t;
            float2 b = __ldg((const float2*)(bias + col));
            int row = m0 + mi * 16 + g;
            *(float2*)(Z + (size_t)row * SZ + col) =
                make_float2(frelu(acc[mi][nj][0] + b.x), frelu(acc[mi][nj][1] + b.y));
            *(float2*)(Z + (size_t)(row + 8) * SZ + col) =
                make_float2(frelu(acc[mi][nj][2] + b.x), frelu(acc[mi][nj][3] + b.y));
        }
}

// ---- small-tile SIMT path (blocks 1-3) ----
template <int KS, int CW>
__device__ __forceinline__ void ldgW16(float r[16], const float* __restrict__ W,
                                       int ldW, int cbase, int kbase) {
#pragma unroll
    for (int j = 0; j < 16; j++) {
        int idx = threadIdx.x + j * NT;
        int c = idx / KS, k = idx % KS;
        r[j] = __ldg(W + (cbase + c) * ldW + (kbase + k));
    }
}
template <int KS, int CW>
__device__ __forceinline__ void stsW16(float* __restrict__ Wb, const float r[16]) {
#pragma unroll
    for (int j = 0; j < 16; j++) {
        int idx = threadIdx.x + j * NT;
        int c = idx / KS, k = idx % KS;
        Wb[k * (CW + 4) + c] = r[j];
    }
}
template <int TP, int PGR, int CW, int KS>
__device__ __forceinline__ void mma2(const float* __restrict__ A, int SA,
                                     const float* __restrict__ Wb,
                                     int pgrp, int cgrp, u64 acc[TP][4]) {
    constexpr int SWB = CW + 4;
    const float* Ap[TP];
#pragma unroll
    for (int i = 0; i < TP; i++) Ap[i] = A + (pgrp + i * PGR) * SA;
    const char* wbase = (const char*)(Wb + cgrp * 8);
#pragma unroll 8
    for (int k = 0; k < KS; k++) {
        ulonglong2 u0 = *(const ulonglong2*)(wbase + (size_t)k * (SWB * 4));
        ulonglong2 u1 = *(const ulonglong2*)(wbase + (size_t)k * (SWB * 4) + 16);
#pragma unroll
        for (int i = 0; i < TP; i++) {
            u64 a2 = splat2(Ap[i][k]);
            acc[i][0] = fma2(a2, u0.x, acc[i][0]);
            acc[i][1] = fma2(a2, u0.y, acc[i][1]);
            acc[i][2] = fma2(a2, u1.x, acc[i][2]);
            acc[i][3] = fma2(a2, u1.y, acc[i][3]);
        }
    }
}

// -------- init: reset max-pool accumulator each replay --------
__global__ void k_init() {
    g_gmax[threadIdx.x] = 0;
}

// ============================================================
// k_prep: split MMA weights into bf16 hi/lo global slab images.
// Image layouts match the smem staging buffers exactly (incl. pads).
// ============================================================
__global__ void k_prep(const float* __restrict__ W4, const float* __restrict__ W5,
                       const float* __restrict__ W6, const float* __restrict__ W7) {
    const int tid = blockIdx.x * blockDim.x + threadIdx.x;
    const int nth = gridDim.x * blockDim.x;
    // block4: 16 slabs [128 rows][36 u32] (KF=64 -> 32 data u32 + 4 pad)
    for (int i = tid; i < 16 * 128 * 36; i += nth) {
        int t = i / (128 * 36), r = i % (128 * 36);
        int c = r / 36, k2 = r % 36;
        uint32_t hi = 0, lo = 0;
        if (k2 < 32) {
            const float* p = W4 + (size_t)((t >> 1) * 128 + c) * 128 + (t & 1) * 64 + 2 * k2;
            split2(make_float2(p[0], p[1]), hi, lo);
        }
        g_w4[t * 9216 + c * 36 + k2] = hi;
        g_w4[t * 9216 + 4608 + c * 36 + k2] = lo;
    }
    // block5: 8 slabs [256][12 u32] (KF=16 -> 8 data + 4 pad)
    for (int i = tid; i < 8 * 256 * 12; i += nth) {
        int t = i / (256 * 12), r = i % (256 * 12);
        int c = r / 12, k2 = r % 12;
        uint32_t hi = 0, lo = 0;
        if (k2 < 8) {
            const float* p = W5 + (size_t)((t >> 2) * 256 + c) * 1088 + (t & 3) * 16 + 2 * k2;
            split2(make_float2(p[0], p[1]), hi, lo);
        }
        g_w5[t * 6144 + c * 12 + k2] = hi;
        g_w5[t * 6144 + 3072 + c * 12 + k2] = lo;
    }
    // block6: 32 slabs [256][12 u32]
    for (int i = tid; i < 32 * 256 * 12; i += nth) {
        int t = i / (256 * 12), r = i % (256 * 12);
        int c = r / 12, k2 = r % 12;
        uint32_t hi = 0, lo = 0;
        if (k2 < 8) {
            const float* p = W6 + (size_t)c * 512 + t * 16 + 2 * k2;
            split2(make_float2(p[0], p[1]), hi, lo);
        }
        g_w6[t * 6144 + c * 12 + k2] = hi;
        g_w6[t * 6144 + 3072 + c * 12 + k2] = lo;
    }
    // block7: 8 slabs [128][20 u32] (KF=32 -> 16 data + 4 pad)
    for (int i = tid; i < 8 * 128 * 20; i += nth) {
        int t = i / (128 * 20), r = i % (128 * 20);
        int c = r / 20, k2 = r % 20;
        uint32_t hi = 0, lo = 0;
        if (k2 < 16) {
            const float* p = W7 + (size_t)c * 256 + t * 32 + 2 * k2;
            split2(make_float2(p[0], p[1]), hi, lo);
        }
        g_w7[t * 5120 + c * 20 + k2] = hi;
        g_w7[t * 5120 + 2560 + c * 20 + k2] = lo;
    }
}

// ============================================================
// Kernel A: blocks 1..3 SIMT + block4 via HMMA on bf16 planes.
// CTA = 128 points, 256 threads.
// ============================================================
#define SMEM1_FLOATS 41536

__global__ __launch_bounds__(NT, 1) void k_front(
    const float* __restrict__ x,
    const float* __restrict__ W1, const float* __restrict__ b1,
    const float* __restrict__ W2, const float* __restrict__ b2,
    const float* __restrict__ W3, const float* __restrict__ b3,
    const float* __restrict__ b4) {
    extern __shared__ float sm[];
    float* a1 = sm;                         // stride 132
    uint32_t* aHi = (uint32_t*)sm;          // 8704 u32, SAH=136 halves (SRU=68)
    uint32_t* aLo = aHi + 8704;
    float* hbuf = sm + 17408;
    float* Wb   = sm + 26112;
    uint32_t* whi32 = (uint32_t*)(sm + 30464);  // 4608 u32 (SWB=72 halves) + lo contiguous
    uint32_t* wlo32 = whi32 + 4608;
    int*   gmax = (int*)(sm + 39680);
    float* cst  = sm + 40704;
    float* w1s = cst;          // 192
    float* b1s = cst + 192;    // 64
    float* xs  = cst + 256;    // 384
    float* b2s = cst + 640;    // 64
    float* b3s = cst + 704;    // 128

    const int tid   = threadIdx.x;
    const int wid   = tid >> 5;
    const int lane  = tid & 31;
    const int pbase = blockIdx.x * 128;

    for (int i = tid; i < 1024; i += NT) gmax[i] = 0;
    for (int i = tid; i < 192; i += NT) w1s[i] = W1[i];
    for (int i = tid; i < 64; i += NT) { b1s[i] = b1[i]; b2s[i] = b2[i]; }
    for (int i = tid; i < 128; i += NT) b3s[i] = b3[i];
    for (int i = tid; i < 384; i += NT) xs[i] = x[pbase * 3 + i];

    float rw[16];
    ldgW16<64, 64>(rw, W2, 64, 0, 0);     // prefetch W2 slab
    __syncthreads();

    // ---- block1: a1 = relu(x @ W1^T + b1)
    for (int idx = tid; idx < 128 * 64; idx += NT) {
        int p = idx >> 6, c = idx & 63;
        float v = fmaf(xs[p * 3 + 2], w1s[c * 3 + 2],
                  fmaf(xs[p * 3 + 1], w1s[c * 3 + 1],
                  fmaf(xs[p * 3 + 0], w1s[c * 3 + 0], b1s[c])));
        a1[p * 132 + c] = frelu(v);
    }
    __syncthreads();

    stsW16<64, 64>(Wb, rw);
    ldgW16<64, 64>(rw, W3, 64, 0, 0);
    __syncthreads();

    const int opg = tid >> 3;  // 0..31
    const int ocg = tid & 7;   // 0..7
    const int oc0 = ocg * 8;

    // ---- block2: h = relu(a1 @ W2^T + b2) -> hbuf (+ g_h)
    {
        u64 acc[4][4];
#pragma unroll
        for (int i = 0; i < 4; i++)
#pragma unroll
            for (int j = 0; j < 4; j++) acc[i][j] = pack2(b2s[oc0 + 2 * j], b2s[oc0 + 2 * j + 1]);
        mma2<4, 32, 64, 64>(a1, 132, Wb, opg, ocg, acc);
#pragma unroll
        for (int i = 0; i < 4; i++)
#pragma unroll
            for (int j = 0; j < 4; j++) {
                float2 f = unpack2(acc[i][j]);
                hbuf[(opg + i * 32) * 68 + oc0 + 2 * j]     = frelu(f.x);
                hbuf[(opg + i * 32) * 68 + oc0 + 2 * j + 1] = frelu(f.y);
            }
    }
    __syncthreads();

    stsW16<64, 64>(Wb, rw);
    ldgW16<64, 64>(rw, W3, 64, 64, 0);
    __syncthreads();

    for (int idx = tid; idx < 128 * 64; idx += NT) {
        int p = idx >> 6, c = idx & 63;
        g_h[(pbase + p) * 64 + c] = hbuf[p * 68 + c];
    }

    // ---- block3 chunk 0 -> a-planes cols 0..63 (overlays dead a1)
    {
        u64 acc[4][4];
#pragma unroll
        for (int i = 0; i < 4; i++)
#pragma unroll
            for (int j = 0; j < 4; j++) acc[i][j] = pack2(b3s[oc0 + 2 * j], b3s[oc0 + 2 * j + 1]);
        mma2<4, 32, 64, 64>(hbuf, 68, Wb, opg, ocg, acc);
#pragma unroll
        for (int i = 0; i < 4; i++)
#pragma unroll
            for (int j = 0; j < 4; j++) {
                float2 f = unpack2(acc[i][j]);
                uint32_t hi, lo;
                split2(make_float2(frelu(f.x), frelu(f.y)), hi, lo);
                int row = opg + i * 32, cp = (oc0 >> 1) + j;
                aHi[row * 68 + cp] = hi;
                aLo[row * 68 + cp] = lo;
            }
    }
    __syncthreads();

    stsW16<64, 64>(Wb, rw);
    uint4 rwp[9];
    ldgP<9>(rwp, g_w4);   // prefetch W4 slab 0 (pre-split image)
    __syncthreads();

    // ---- block3 chunk 1 -> a-planes cols 64..127
    {
        u64 acc[4][4];
#pragma unroll
        for (int i = 0; i < 4; i++)
#pragma unroll
            for (int j = 0; j < 4; j++) acc[i][j] = pack2(b3s[64 + oc0 + 2 * j], b3s[64 + oc0 + 2 * j + 1]);
        mma2<4, 32, 64, 64>(hbuf, 68, Wb, opg, ocg, acc);
#pragma unroll
        for (int i = 0; i < 4; i++)
#pragma unroll
            for (int j = 0; j < 4; j++) {
                float2 f = unpack2(acc[i][j]);
                uint32_t hi, lo;
                split2(make_float2(frelu(f.x), frelu(f.y)), hi, lo);
                int row = opg + i * 32, cp = 32 + (oc0 >> 1) + j;
                aHi[row * 68 + cp] = hi;
                aLo[row * 68 + cp] = lo;
            }
    }

    // ---- block4: 8 chunks of 128 out-ch via HMMA on planes; only max kept.
    const uint32_t aHi_a = smem_to_u32(aHi);
    const uint32_t aLo_a = smem_to_u32(aLo);
    const uint32_t whi_a = smem_to_u32(whi32);
    const uint32_t wlo_a = smem_to_u32(wlo32);
    const int m0 = (wid & 3) * 32;   // 4 M-warps
    const int n0 = (wid >> 2) * 64;  // 2 N-warps

    for (int cc = 0; cc < 8; cc++) {
        float acc[2][8][4];
#pragma unroll
        for (int mi = 0; mi < 2; mi++)
#pragma unroll
            for (int nj = 0; nj < 8; nj++)
#pragma unroll
                for (int q = 0; q < 4; q++) acc[mi][nj][q] = 0.f;

        for (int s = 0; s < 2; s++) {
            __syncthreads();
            stsP<9>(whi32, rwp);
            int t = cc * 2 + s + 1;
            if (t < 16) ldgP<9>(rwp, g_w4 + t * 9216);
            __syncthreads();
#pragma unroll
            for (int q = 0; q < 4; q++)
                gemm_kstep_p<4>(aHi_a, aLo_a, 136, m0, whi_a, wlo_a, 72,
                                n0, q * 16, s * 64 + q * 16, lane, acc);
        }

        // epilogue: in-thread max over rows, shfl over groups, bias+relu, atomicMax
        float m0v[8], m1v[8];
#pragma unroll
        for (int nj = 0; nj < 8; nj++) {
            m0v[nj] = fmaxf(fmaxf(acc[0][nj][0], acc[0][nj][2]),
                            fmaxf(acc[1][nj][0], acc[1][nj][2]));
            m1v[nj] = fmaxf(fmaxf(acc[0][nj][1], acc[0][nj][3]),
                            fmaxf(acc[1][nj][1], acc[1][nj][3]));
        }
#pragma unroll
        for (int m = 4; m < 32; m <<= 1)
#pragma unroll
            for (int nj = 0; nj < 8; nj++) {
                m0v[nj] = fmaxf(m0v[nj], __shfl_xor_sync(0xffffffffu, m0v[nj], m));
                m1v[nj] = fmaxf(m1v[nj], __shfl_xor_sync(0xffffffffu, m1v[nj], m));
            }
        if ((lane >> 2) == 0) {
            int t = lane & 3;
#pragma unroll
            for (int nj = 0; nj < 8; nj++) {
                int col = cc * 128 + n0 + nj * 8 + 2 * t;
                float2 b = __ldg((const float2*)(b4 + col));
                atomicMax(&gmax[col],     __float_as_int(frelu(m0v[nj] + b.x)));
                atomicMax(&gmax[col + 1], __float_as_int(frelu(m1v[nj] + b.y)));
            }
        }
    }
    __syncthreads();
    for (int i = tid; i < 1024; i += NT) atomicMax(&g_gmax[i], gmax[i]);
}

// ============================================================
// Kernel B: c5[j] = b5[j] + sum_i W5[j][64+i] * g[i]
// ============================================================
__global__ void k_c5(const float* __restrict__ W5, const float* __restrict__ b5) {
    __shared__ float gs[1024];
    const int tid = threadIdx.x;
    for (int i = tid; i < 1024; i += 256) gs[i] = __int_as_float(g_gmax[i]);
    __syncthreads();
    const int j = blockIdx.x * 64 + (tid >> 2);
    const int q = tid & 3;
    const float* wr = W5 + j * 1088 + 64 + q * 256;
    const float* gr = gs + q * 256;
    float s = 0.f;
#pragma unroll 8
    for (int i = 0; i < 256; i++) s = fmaf(wr[i], gr[i], s);
    s += __shfl_xor_sync(0xffffffffu, s, 1);
    s += __shfl_xor_sync(0xffffffffu, s, 2);
    if (q == 0) g_c5[j] = s + b5[j];
}

// ============================================================
// Kernel C: blocks 5..8 via HMMA on bf16 planes. CTA = 64 pts, 256 thr.
// ============================================================
#define SMEM3_FLOATS 56320

__global__ __launch_bounds__(NT, 1) void k_back(
    const float* __restrict__ b6, const float* __restrict__ b7,
    const float* __restrict__ W8, const float* __restrict__ b8,
    float* __restrict__ out) {
    extern __shared__ float sm[];
    uint32_t* z5Hi = (uint32_t*)sm;           // 16640 u32, SAH=520 (SRU=260)
    uint32_t* z5Lo = z5Hi + 16640;
    uint32_t* z6Hi = (uint32_t*)(sm + 33280); // 8448 u32, SAH=264 (SRU=132)
    uint32_t* z6Lo = z6Hi + 8448;
    uint32_t* hHi  = z6Hi;                    // overlay: 2304 u32, SAH=72 (SRU=36)
    uint32_t* hLo  = hHi + 2304;
    uint32_t* whi32 = (uint32_t*)(sm + 50176); // slab image (hi || lo)
    float* z7 = sm;                           // stride 132 (overlays z5 planes)

    const int tid   = threadIdx.x;
    const int wid   = tid >> 5;
    const int lane  = tid & 31;
    const int pbase = blockIdx.x * 64;

    // load h -> bf16 planes
    for (int idx = tid; idx < 64 * 32; idx += NT) {
        int p = idx >> 5, c2 = idx & 31;
        float2 v = *(const float2*)(g_h + (size_t)(pbase + p) * 64 + 2 * c2);
        uint32_t hi, lo;
        split2(v, hi, lo);
        hHi[p * 36 + c2] = hi;
        hLo[p * 36 + c2] = lo;
    }

    uint4 rwp[6];
    ldgP<6>(rwp, g_w5);   // prefetch W5a slab 0
    __syncthreads();

    const uint32_t z5Hi_a = smem_to_u32(z5Hi);
    const uint32_t z5Lo_a = smem_to_u32(z5Lo);
    const uint32_t z6Hi_a = smem_to_u32(z6Hi);
    const uint32_t z6Lo_a = smem_to_u32(z6Lo);
    const uint32_t hHi_a  = smem_to_u32(hHi);
    const uint32_t hLo_a  = smem_to_u32(hLo);
    const uint32_t whi_a  = smem_to_u32(whi32);
    const uint32_t wlo_a  = whi_a + 3072 * 4;   // blocks 5/6 lo offset
    const uint32_t wlo7_a = whi_a + 2560 * 4;   // block7 lo offset
    const int m0 = (wid & 1) * 32;   // 2 M-warps
    const int wn = wid >> 1;         // 4 N-warps

    // ---- block5: z5 = relu(h @ W5a^T + c5). 2 N-passes of 256, K=64.
    for (int cc = 0; cc < 2; cc++) {
        float acc[2][8][4];
#pragma unroll
        for (int mi = 0; mi < 2; mi++)
#pragma unroll
            for (int nj = 0; nj < 8; nj++)
#pragma unroll
                for (int q = 0; q < 4; q++) acc[mi][nj][q] = 0.f;
        for (int s = 0; s < 4; s++) {
            __syncthreads();
            stsP<6>(whi32, rwp);
            int t = cc * 4 + s + 1;
            if (t < 8)       ldgP<6>(rwp, g_w5 + t * 6144);
            else if (t == 8) ldgP<6>(rwp, g_w6);
            __syncthreads();
            gemm_kstep_p<4>(hHi_a, hLo_a, 72, m0, whi_a, wlo_a, 24,
                            wn * 64, 0, s * 16, lane, acc);
        }
        epi_store_p<8>(z5Hi, z5Lo, 260, m0, cc * 256 + wn * 64, g_c5, acc, lane);
    }

    // ---- block6: z6 = relu(z5 @ W6^T + b6). N=256, K=512.
    {
        float acc[2][8][4];
#pragma unroll
        for (int mi = 0; mi < 2; mi++)
#pragma unroll
            for (int nj = 0; nj < 8; nj++)
#pragma unroll
                for (int q = 0; q < 4; q++) acc[mi][nj][q] = 0.f;
        for (int s = 0; s < 32; s++) {
            __syncthreads();
            stsP<6>(whi32, rwp);
            int t = s + 1;
            if (t < 32) ldgP<6>(rwp, g_w6 + t * 6144);
            else        ldgP<5>(rwp, g_w7);   // block7 slab 0 (5 uint4)
            __syncthreads();
            gemm_kstep_p<4>(z5Hi_a, z5Lo_a, 520, m0, whi_a, wlo_a, 24,
                            wn * 64, 0, s * 16, lane, acc);
        }
        epi_store_p<8>(z6Hi, z6Lo, 132, m0, wn * 64, b6, acc, lane);
    }

    // ---- block7: z7 = relu(z6 @ W7^T + b7). N=128, K=256. fp32 out over z5.
    {
        float acc[2][4][4];
#pragma unroll
        for (int mi = 0; mi < 2; mi++)
#pragma unroll
            for (int nj = 0; nj < 4; nj++)
#pragma unroll
                for (int q = 0; q < 4; q++) acc[mi][nj][q] = 0.f;
        for (int s = 0; s < 8; s++) {
            __syncthreads();
            stsP<5>(whi32, rwp);
            if (s < 7) ldgP<5>(rwp, g_w7 + (s + 1) * 5120);
            __syncthreads();
            gemm_kstep_p<2>(z6Hi_a, z6Lo_a, 264, m0, whi_a, wlo7_a, 40,
                            wn * 32, 0,  s * 32,      lane, acc);
            gemm_kstep_p<2>(z6Hi_a, z6Lo_a, 264, m0, whi_a, wlo7_a, 40,
                            wn * 32, 16, s * 32 + 16, lane, acc);
        }
        __syncthreads();   // z5 planes dead; safe to overlay z7 fp32
        epi_store<4>(z7, 132, m0, wn * 32, b7, acc, lane);
    }
    __syncthreads();

    // ---- block8: out = z7 @ W8^T + b8 (no relu)
    if (tid < 64) {
        const float* zr = z7 + tid * 132;
        float s = __ldg(b8);
#pragma unroll 8
        for (int k = 0; k < 128; k++) s = fmaf(zr[k], __ldg(W8 + k), s);
        out[pbase + tid] = s;
    }
}

// ============================================================
extern "C" void kernel_launch(void* const* d_in, const int* in_sizes, int n_in,
                              void* d_out, int out_size) {
    const float* x  = (const float*)d_in[0];
    const float* W1 = (const float*)d_in[1];  const float* b1 = (const float*)d_in[2];
    const float* W2 = (const float*)d_in[3];  const float* b2 = (const float*)d_in[4];
    const float* W3 = (const float*)d_in[5];  const float* b3 = (const float*)d_in[6];
    const float* W4 = (const float*)d_in[7];  const float* b4 = (const float*)d_in[8];
    const float* W5 = (const float*)d_in[9];  const float* b5 = (const float*)d_in[10];
    const float* W6 = (const float*)d_in[11]; const float* b6 = (const float*)d_in[12];
    const float* W7 = (const float*)d_in[13]; const float* b7 = (const float*)d_in[14];
    const float* W8 = (const float*)d_in[15]; const float* b8 = (const float*)d_in[16];
    float* out = (float*)d_out;

    const int n = in_sizes[0] / 3;  // 65536

    const int smem1 = SMEM1_FLOATS * (int)sizeof(float);
    const int smem3 = SMEM3_FLOATS * (int)sizeof(float);
    cudaFuncSetAttribute(k_front, cudaFuncAttributeMaxDynamicSharedMemorySize, smem1);
    cudaFuncSetAttribute(k_back,  cudaFuncAttributeMaxDynamicSharedMemorySize, smem3);

    k_init<<<1, 1024>>>();
    k_prep<<<64, 256>>>(W4, W5, W6, W7);
    k_front<<<n / 128, NT, smem1>>>(x, W1, b1, W2, b2, W3, b3, b4);
    k_c5<<<8, 256>>>(W5, b5);
    k_back<<<n / 64, NT, smem3>>>(b6, b7, W8, b8, out);
}

// round 10
// speedup vs baseline: 3.6309x; 1.1597x over previous
#include <cuda_runtime.h>
#include <cuda_bf16.h>
#include <cstdint>

#define NT 256

// -------- persistent device scratch (no allocs allowed) --------
__device__ int   g_gmax[1024];      // global max-pool accumulator (float bits, >=0)
__device__ float g_c5[512];         // c5 = b5 + W5[:,64:] @ g

// h (block2 output) as bf16 hi/lo plane images: per 128-pt front CTA,
// [128 rows][36 u32] hi plane (4608 u32) || lo plane (4608 u32)
__device__ __align__(16) uint32_t g_hp[512 * 9216];

// pre-split bf16 weight planes, stored as exact smem slab images (hi plane || lo plane)
__device__ __align__(16) uint32_t g_w2[4608];       // block2: [64][36u32] x2
__device__ __align__(16) uint32_t g_w3[9216];       // block3: [128][36u32] x2
__device__ __align__(16) uint32_t g_w4[16 * 9216];  // block4: 16 slabs [128][36u32] x2
__device__ __align__(16) uint32_t g_w5[8 * 6144];   // block5: 8 slabs [256][12u32] x2
__device__ __align__(16) uint32_t g_w6[32 * 6144];  // block6: 32 slabs [256][12u32] x2
__device__ __align__(16) uint32_t g_w7[8 * 5120];   // block7: 8 slabs [128][20u32] x2

__device__ __forceinline__ float frelu(float v) { return v > 0.f ? v : 0.f; }

// ============================================================
// HMMA (mma.sync) machinery — compiles at plain sm_103 target.
// ============================================================
__device__ __forceinline__ void mma16816(float* c, const uint32_t* a, const uint32_t* b) {
    asm volatile(
        "mma.sync.aligned.m16n8k16.row.col.f32.bf16.bf16.f32 "
        "{%0,%1,%2,%3}, {%4,%5,%6,%7}, {%8,%9}, {%0,%1,%2,%3};"
        : "+f"(c[0]), "+f"(c[1]), "+f"(c[2]), "+f"(c[3])
        : "r"(a[0]), "r"(a[1]), "r"(a[2]), "r"(a[3]), "r"(b[0]), "r"(b[1]));
}
__device__ __forceinline__ void ldsm4(uint32_t r[4], uint32_t addr) {
    asm volatile("ldmatrix.sync.aligned.m8n8.x4.shared.b16 {%0,%1,%2,%3}, [%4];"
                 : "=r"(r[0]), "=r"(r[1]), "=r"(r[2]), "=r"(r[3]) : "r"(addr));
}
__device__ __forceinline__ uint32_t smem_to_u32(const void* p) {
    uint32_t a;
    asm("{ .reg .u64 t; cvta.to.shared.u64 t, %1; cvt.u32.u64 %0, t; }" : "=r"(a) : "l"(p));
    return a;
}

// split a float2 into packed bf16x2 hi and lo (residual) parts.
__device__ __forceinline__ void split2(float2 v, uint32_t& hi, uint32_t& lo) {
    uint32_t h;
    asm("cvt.rn.bf16x2.f32 %0, %1, %2;" : "=r"(h) : "f"(v.y), "f"(v.x));
    float h0 = __uint_as_float(h << 16);
    float h1 = __uint_as_float(h & 0xFFFF0000u);
    float l0 = v.x - h0, l1 = v.y - h1;
    asm("cvt.rn.bf16x2.f32 %0, %1, %2;" : "=r"(lo) : "f"(l1), "f"(l0));
    hi = h;
}

// ldmatrix.x4 A-fragment load from a bf16 plane (row-major, SAH halves/row).
__device__ __forceinline__ void ldAm(uint32_t r[4], uint32_t plane, int SAH,
                                     int row0, int kabs, int lane) {
    int j = lane >> 3, rr = lane & 7;
    int row = row0 + ((j & 1) << 3) + rr;
    int col = kabs + ((j >> 1) << 3);
    ldsm4(r, plane + (uint32_t)(row * SAH + col) * 2);
}

// One k16 step of warp GEMM on bf16 planes: 32 rows x (NTILES*16) cols, 3-term split.
template <int NTILES>
__device__ __forceinline__ void gemm_kstep_p(uint32_t aHi, uint32_t aLo, int SAH, int m0,
                                             uint32_t whi, uint32_t wlo, int SWB,
                                             int n0loc, int k0loc, int kabs, int lane,
                                             float acc[2][NTILES * 2][4]) {
    uint32_t ahi[2][4], alo[2][4];
    ldAm(ahi[0], aHi, SAH, m0,      kabs, lane);
    ldAm(ahi[1], aHi, SAH, m0 + 16, kabs, lane);
    ldAm(alo[0], aLo, SAH, m0,      kabs, lane);
    ldAm(alo[1], aLo, SAH, m0 + 16, kabs, lane);
    uint32_t bh[NTILES][4], bl[NTILES][4];
    const int nl = n0loc + (lane & 7) + ((lane >> 4) << 3);
    const int kk = k0loc + (((lane >> 3) & 1) << 3);
#pragma unroll
    for (int nt = 0; nt < NTILES; nt++) {
        uint32_t off = (uint32_t)((nl + nt * 16) * SWB + kk) * 2;
        ldsm4(bh[nt], whi + off);
        ldsm4(bl[nt], wlo + off);
    }
#pragma unroll
    for (int mi = 0; mi < 2; mi++)
#pragma unroll
        for (int nt = 0; nt < NTILES; nt++) {
            mma16816(acc[mi][2 * nt],     ahi[mi], &bh[nt][0]);
            mma16816(acc[mi][2 * nt + 1], ahi[mi], &bh[nt][2]);
        }
#pragma unroll
    for (int mi = 0; mi < 2; mi++)
#pragma unroll
        for (int nt = 0; nt < NTILES; nt++) {
            mma16816(acc[mi][2 * nt],     ahi[mi], &bl[nt][0]);
            mma16816(acc[mi][2 * nt + 1], ahi[mi], &bl[nt][2]);
        }
#pragma unroll
    for (int mi = 0; mi < 2; mi++)
#pragma unroll
        for (int nt = 0; nt < NTILES; nt++) {
            mma16816(acc[mi][2 * nt],     alo[mi], &bh[nt][0]);
            mma16816(acc[mi][2 * nt + 1], alo[mi], &bh[nt][2]);
        }
}

// ---- slab staging: pure uint4 copy from pre-split global images ----
template <int NV>
__device__ __forceinline__ void ldgP(uint4 r[NV], const uint32_t* __restrict__ src) {
#pragma unroll
    for (int j = 0; j < NV; j++)
        r[j] = ((const uint4*)src)[threadIdx.x + j * NT];
}
template <int NV>
__device__ __forceinline__ void stsP(uint32_t* __restrict__ dst, const uint4 r[NV]) {
#pragma unroll
    for (int j = 0; j < NV; j++)
        ((uint4*)dst)[threadIdx.x + j * NT] = r[j];
}

// Epilogue: relu(acc + bias) -> bf16 hi/lo planes (u32-addressed, SRU u32/row).
template <int NJ>
__device__ __forceinline__ void epi_store_p(uint32_t* __restrict__ hiP,
                                            uint32_t* __restrict__ loP, int SRU,
                                            int m0, int nbase, const float* __restrict__ bias,
                                            float acc[2][NJ][4], int lane) {
    int g = lane >> 2, t = lane & 3;
#pragma unroll
    for (int mi = 0; mi < 2; mi++)
#pragma unroll
        for (int nj = 0; nj < NJ; nj++) {
            int col = nbase + nj * 8 + 2 * t;
            float2 b = __ldg((const float2*)(bias + col));
            int row = m0 + mi * 16 + g;
            uint32_t h0, l0, h1, l1;
            split2(make_float2(frelu(acc[mi][nj][0] + b.x), frelu(acc[mi][nj][1] + b.y)), h0, l0);
            split2(make_float2(frelu(acc[mi][nj][2] + b.x), frelu(acc[mi][nj][3] + b.y)), h1, l1);
            int cp = col >> 1;
            hiP[row * SRU + cp] = h0;       loP[row * SRU + cp] = l0;
            hiP[(row + 8) * SRU + cp] = h1; loP[(row + 8) * SRU + cp] = l1;
        }
}
// Epilogue: relu(acc + bias) -> fp32 smem (for block7 -> block8)
template <int NJ>
__device__ __forceinline__ void epi_store(float* __restrict__ Z, int SZ, int m0, int nbase,
                                          const float* __restrict__ bias,
                                          float acc[2][NJ][4], int lane) {
    int g = lane >> 2, t = lane & 3;
#pragma unroll
    for (int mi = 0; mi < 2; mi++)
#pragma unroll
        for (int nj = 0; nj < NJ; nj++) {
            int col = nbase + nj * 8 + 2 * t;
            float2 b = __ldg((const float2*)(bias + col));
            int row = m0 + mi * 16 + g;
            *(float2*)(Z + (size_t)row * SZ + col) =
                make_float2(frelu(acc[mi][nj][0] + b.x), frelu(acc[mi][nj][1] + b.y));
            *(float2*)(Z + (size_t)(row + 8) * SZ + col) =
                make_float2(frelu(acc[mi][nj][2] + b.x), frelu(acc[mi][nj][3] + b.y));
        }
}

// -------- init: reset max-pool accumulator each replay --------
__global__ void k_init() {
    g_gmax[threadIdx.x] = 0;
}

// ============================================================
// k_prep: split MMA weights into bf16 hi/lo global slab images.
// ============================================================
__global__ void k_prep(const float* __restrict__ W2, const float* __restrict__ W3,
                       const float* __restrict__ W4, const float* __restrict__ W5,
                       const float* __restrict__ W6, const float* __restrict__ W7) {
    const int tid = blockIdx.x * blockDim.x + threadIdx.x;
    const int nth = gridDim.x * blockDim.x;
    // block2: [64 rows][36 u32], K=64
    for (int i = tid; i < 64 * 36; i += nth) {
        int c = i / 36, k2 = i % 36;
        uint32_t hi = 0, lo = 0;
        if (k2 < 32) {
            const float* p = W2 + (size_t)c * 64 + 2 * k2;
            split2(make_float2(p[0], p[1]), hi, lo);
        }
        g_w2[c * 36 + k2] = hi;
        g_w2[2304 + c * 36 + k2] = lo;
    }
    // block3: [128 rows][36 u32], K=64
    for (int i = tid; i < 128 * 36; i += nth) {
        int c = i / 36, k2 = i % 36;
        uint32_t hi = 0, lo = 0;
        if (k2 < 32) {
            const float* p = W3 + (size_t)c * 64 + 2 * k2;
            split2(make_float2(p[0], p[1]), hi, lo);
        }
        g_w3[c * 36 + k2] = hi;
        g_w3[4608 + c * 36 + k2] = lo;
    }
    // block4: 16 slabs [128 rows][36 u32] (KF=64 -> 32 data u32 + 4 pad)
    for (int i = tid; i < 16 * 128 * 36; i += nth) {
        int t = i / (128 * 36), r = i % (128 * 36);
        int c = r / 36, k2 = r % 36;
        uint32_t hi = 0, lo = 0;
        if (k2 < 32) {
            const float* p = W4 + (size_t)((t >> 1) * 128 + c) * 128 + (t & 1) * 64 + 2 * k2;
            split2(make_float2(p[0], p[1]), hi, lo);
        }
        g_w4[t * 9216 + c * 36 + k2] = hi;
        g_w4[t * 9216 + 4608 + c * 36 + k2] = lo;
    }
    // block5: 8 slabs [256][12 u32] (KF=16 -> 8 data + 4 pad)
    for (int i = tid; i < 8 * 256 * 12; i += nth) {
        int t = i / (256 * 12), r = i % (256 * 12);
        int c = r / 12, k2 = r % 12;
        uint32_t hi = 0, lo = 0;
        if (k2 < 8) {
            const float* p = W5 + (size_t)((t >> 2) * 256 + c) * 1088 + (t & 3) * 16 + 2 * k2;
            split2(make_float2(p[0], p[1]), hi, lo);
        }
        g_w5[t * 6144 + c * 12 + k2] = hi;
        g_w5[t * 6144 + 3072 + c * 12 + k2] = lo;
    }
    // block6: 32 slabs [256][12 u32]
    for (int i = tid; i < 32 * 256 * 12; i += nth) {
        int t = i / (256 * 12), r = i % (256 * 12);
        int c = r / 12, k2 = r % 12;
        uint32_t hi = 0, lo = 0;
        if (k2 < 8) {
            const float* p = W6 + (size_t)c * 512 + t * 16 + 2 * k2;
            split2(make_float2(p[0], p[1]), hi, lo);
        }
        g_w6[t * 6144 + c * 12 + k2] = hi;
        g_w6[t * 6144 + 3072 + c * 12 + k2] = lo;
    }
    // block7: 8 slabs [128][20 u32] (KF=32 -> 16 data + 4 pad)
    for (int i = tid; i < 8 * 128 * 20; i += nth) {
        int t = i / (128 * 20), r = i % (128 * 20);
        int c = r / 20, k2 = r % 20;
        uint32_t hi = 0, lo = 0;
        if (k2 < 16) {
            const float* p = W7 + (size_t)c * 256 + t * 32 + 2 * k2;
            split2(make_float2(p[0], p[1]), hi, lo);
        }
        g_w7[t * 5120 + c * 20 + k2] = hi;
        g_w7[t * 5120 + 2560 + c * 20 + k2] = lo;
    }
}

// ============================================================
// Kernel A: block1 SIMT-lite + blocks 2,3,4 via HMMA on bf16 planes.
// CTA = 128 points, 256 threads.
// smem u32 layout:
//   a1Hi @0 (4608: 128x36)  a1Lo @4608            (w3 image overlays after block2)
//   hHi  @9216 (4608)       hLo @13824
//   aHi  @18432 (8704: 128x68)  aLo @27136
//   w4 slab @35840 (9216)
//   w2 image @45056 (4608)
//   gmax @49664 (1024)
//   consts @50688 (640 floats: w1s 192 | b1s 64 | xs 384)
// ============================================================
#define SMEM1_FLOATS 51328

__global__ __launch_bounds__(NT, 1) void k_front(
    const float* __restrict__ x,
    const float* __restrict__ W1, const float* __restrict__ b1,
    const float* __restrict__ b2, const float* __restrict__ b3,
    const float* __restrict__ b4) {
    extern __shared__ float sm[];
    uint32_t* u = (uint32_t*)sm;
    uint32_t* a1Hi = u;            // SRU 36
    uint32_t* a1Lo = u + 4608;
    uint32_t* w3s  = u;            // overlay (hi @0, lo @4608)
    uint32_t* hHi  = u + 9216;     // SRU 36
    uint32_t* hLo  = u + 13824;
    uint32_t* aHi  = u + 18432;    // SRU 68
    uint32_t* aLo  = u + 27136;
    uint32_t* w4s  = u + 35840;    // 9216 (hi 4608 || lo 4608)
    uint32_t* w2s  = u + 45056;    // 4608 (hi 2304 || lo 2304)
    int*   gmax = (int*)(u + 49664);
    float* cst  = sm + 50688;
    float* w1s = cst;          // 192
    float* b1s = cst + 192;    // 64
    float* xs  = cst + 256;    // 384

    const int tid   = threadIdx.x;
    const int wid   = tid >> 5;
    const int lane  = tid & 31;
    const int pbase = blockIdx.x * 128;

    for (int i = tid; i < 1024; i += NT) gmax[i] = 0;
    for (int i = tid; i < 192; i += NT) w1s[i] = W1[i];
    for (int i = tid; i < 64; i += NT) b1s[i] = b1[i];
    for (int i = tid; i < 384; i += NT) xs[i] = x[pbase * 3 + i];
    for (int i = tid; i < 1152; i += NT)
        ((uint4*)w2s)[i] = ((const uint4*)g_w2)[i];
    __syncthreads();

    // ---- block1: a1 = relu(x @ W1^T + b1) -> a1 planes
    for (int idx = tid; idx < 128 * 32; idx += NT) {
        int p = idx >> 5, c2 = idx & 31;
        int c = 2 * c2;
        float v0 = fmaf(xs[p * 3 + 2], w1s[c * 3 + 2],
                   fmaf(xs[p * 3 + 1], w1s[c * 3 + 1],
                   fmaf(xs[p * 3 + 0], w1s[c * 3 + 0], b1s[c])));
        float v1 = fmaf(xs[p * 3 + 2], w1s[c * 3 + 5],
                   fmaf(xs[p * 3 + 1], w1s[c * 3 + 4],
                   fmaf(xs[p * 3 + 0], w1s[c * 3 + 3], b1s[c + 1])));
        uint32_t hi, lo;
        split2(make_float2(frelu(v0), frelu(v1)), hi, lo);
        a1Hi[p * 36 + c2] = hi;
        a1Lo[p * 36 + c2] = lo;
    }
    __syncthreads();

    const uint32_t a1Hi_a = smem_to_u32(a1Hi);
    const uint32_t a1Lo_a = smem_to_u32(a1Lo);
    const uint32_t hHi_a  = smem_to_u32(hHi);
    const uint32_t hLo_a  = smem_to_u32(hLo);
    const uint32_t aHi_a  = smem_to_u32(aHi);
    const uint32_t aLo_a  = smem_to_u32(aLo);
    const uint32_t w2hi_a = smem_to_u32(w2s);
    const uint32_t w3hi_a = smem_to_u32(w3s);
    const uint32_t w4hi_a = smem_to_u32(w4s);
    const int m0 = (wid & 3) * 32;   // 4 M-warps
    const int wn = wid >> 2;         // 2 N-warps

    // ---- block2: h = relu(a1 @ W2^T + b2) -> h planes, K=64, N=64
    {
        float acc[2][4][4];
#pragma unroll
        for (int mi = 0; mi < 2; mi++)
#pragma unroll
            for (int nj = 0; nj < 4; nj++)
#pragma unroll
                for (int q = 0; q < 4; q++) acc[mi][nj][q] = 0.f;
#pragma unroll
        for (int s = 0; s < 4; s++)
            gemm_kstep_p<2>(a1Hi_a, a1Lo_a, 72, m0, w2hi_a, w2hi_a + 2304 * 4, 72,
                            wn * 32, s * 16, s * 16, lane, acc);
        epi_store_p<4>(hHi, hLo, 36, m0, wn * 32, b2, acc, lane);
    }
    __syncthreads();

    // h planes -> global image; w3 image -> smem (a1 dead)
    {
        uint4* dst = (uint4*)(g_hp + (size_t)blockIdx.x * 9216);
        const uint4* srcH = (const uint4*)hHi;
        for (int i = tid; i < 2304; i += NT) dst[i] = srcH[i];
        for (int i = tid; i < 2304; i += NT)
            ((uint4*)w3s)[i] = ((const uint4*)g_w3)[i];
    }
    __syncthreads();

    // ---- block3: a3 = relu(h @ W3^T + b3) -> a planes, K=64, N=128
    uint4 rwp[9];
    {
        float acc[2][8][4];
#pragma unroll
        for (int mi = 0; mi < 2; mi++)
#pragma unroll
            for (int nj = 0; nj < 8; nj++)
#pragma unroll
                for (int q = 0; q < 4; q++) acc[mi][nj][q] = 0.f;
#pragma unroll
        for (int s = 0; s < 4; s++)
            gemm_kstep_p<4>(hHi_a, hLo_a, 72, m0, w3hi_a, w3hi_a + 4608 * 4, 72,
                            wn * 64, s * 16, s * 16, lane, acc);
        ldgP<9>(rwp, g_w4);   // prefetch W4 slab 0 (overlaps epilogue)
        epi_store_p<8>(aHi, aLo, 68, m0, wn * 64, b3, acc, lane);
    }

    // ---- block4: 8 chunks of 128 out-ch via HMMA on planes; only max kept.
    const uint32_t wlo4_a = w4hi_a + 4608 * 4;
    const int n0 = wn * 64;

    for (int cc = 0; cc < 8; cc++) {
        float acc[2][8][4];
#pragma unroll
        for (int mi = 0; mi < 2; mi++)
#pragma unroll
            for (int nj = 0; nj < 8; nj++)
#pragma unroll
                for (int q = 0; q < 4; q++) acc[mi][nj][q] = 0.f;

        for (int s = 0; s < 2; s++) {
            __syncthreads();
            stsP<9>(w4s, rwp);
            int t = cc * 2 + s + 1;
            if (t < 16) ldgP<9>(rwp, g_w4 + t * 9216);
            __syncthreads();
#pragma unroll
            for (int q = 0; q < 4; q++)
                gemm_kstep_p<4>(aHi_a, aLo_a, 136, m0, w4hi_a, wlo4_a, 72,
                                n0, q * 16, s * 64 + q * 16, lane, acc);
        }

        float m0v[8], m1v[8];
#pragma unroll
        for (int nj = 0; nj < 8; nj++) {
            m0v[nj] = fmaxf(fmaxf(acc[0][nj][0], acc[0][nj][2]),
                            fmaxf(acc[1][nj][0], acc[1][nj][2]));
            m1v[nj] = fmaxf(fmaxf(acc[0][nj][1], acc[0][nj][3]),
                            fmaxf(acc[1][nj][1], acc[1][nj][3]));
        }
#pragma unroll
        for (int m = 4; m < 32; m <<= 1)
#pragma unroll
            for (int nj = 0; nj < 8; nj++) {
                m0v[nj] = fmaxf(m0v[nj], __shfl_xor_sync(0xffffffffu, m0v[nj], m));
                m1v[nj] = fmaxf(m1v[nj], __shfl_xor_sync(0xffffffffu, m1v[nj], m));
            }
        if ((lane >> 2) == 0) {
            int t = lane & 3;
#pragma unroll
            for (int nj = 0; nj < 8; nj++) {
                int col = cc * 128 + n0 + nj * 8 + 2 * t;
                float2 b = __ldg((const float2*)(b4 + col));
                atomicMax(&gmax[col],     __float_as_int(frelu(m0v[nj] + b.x)));
                atomicMax(&gmax[col + 1], __float_as_int(frelu(m1v[nj] + b.y)));
            }
        }
    }
    __syncthreads();
    for (int i = tid; i < 1024; i += NT) atomicMax(&g_gmax[i], gmax[i]);
}

// ============================================================
// Kernel B: c5[j] = b5[j] + sum_i W5[j][64+i] * g[i]
// grid 64 x 256: one warp per output j, coalesced lane-strided reads.
// ============================================================
__global__ void k_c5(const float* __restrict__ W5, const float* __restrict__ b5) {
    __shared__ float gs[1024];
    const int tid = threadIdx.x;
    for (int i = tid; i < 1024; i += 256) gs[i] = __int_as_float(g_gmax[i]);
    __syncthreads();
    const int w = tid >> 5, lane = tid & 31;
    const int j = blockIdx.x * 8 + w;
    const float* wr = W5 + (size_t)j * 1088 + 64;
    float s = 0.f;
#pragma unroll
    for (int i = 0; i < 32; i++) s = fmaf(wr[lane + 32 * i], gs[lane + 32 * i], s);
#pragma unroll
    for (int m = 16; m; m >>= 1) s += __shfl_xor_sync(0xffffffffu, s, m);
    if (lane == 0) g_c5[j] = s + b5[j];
}

// ============================================================
// Kernel C: blocks 5..8 via HMMA on bf16 planes. CTA = 64 pts, 256 thr.
// ============================================================
#define SMEM3_FLOATS 56320

__global__ __launch_bounds__(NT, 1) void k_back(
    const float* __restrict__ b6, const float* __restrict__ b7,
    const float* __restrict__ W8, const float* __restrict__ b8,
    float* __restrict__ out) {
    extern __shared__ float sm[];
    uint32_t* z5Hi = (uint32_t*)sm;           // 16640 u32, SAH=520 (SRU=260)
    uint32_t* z5Lo = z5Hi + 16640;
    uint32_t* z6Hi = (uint32_t*)(sm + 33280); // 8448 u32, SAH=264 (SRU=132)
    uint32_t* z6Lo = z6Hi + 8448;
    uint32_t* hHi  = z6Hi;                    // overlay: 2304 u32, SAH=72 (SRU=36)
    uint32_t* hLo  = hHi + 2304;
    uint32_t* whi32 = (uint32_t*)(sm + 50176); // slab image (hi || lo)
    float* z7 = sm;                           // stride 132 (overlays z5 planes)

    const int tid   = threadIdx.x;
    const int wid   = tid >> 5;
    const int lane  = tid & 31;
    const int pbase = blockIdx.x * 64;

    // copy h planes from pre-split global image (exact same bits as before)
    {
        const uint32_t* hiSrc = g_hp + (size_t)(blockIdx.x >> 1) * 9216 + (blockIdx.x & 1) * 2304;
        const uint4* s0 = (const uint4*)hiSrc;
        const uint4* s1 = (const uint4*)(hiSrc + 4608);
        uint4* d0 = (uint4*)hHi;
        uint4* d1 = (uint4*)hLo;
        for (int i = tid; i < 576; i += NT) { d0[i] = s0[i]; d1[i] = s1[i]; }
    }

    uint4 rwp[6];
    ldgP<6>(rwp, g_w5);   // prefetch W5a slab 0
    __syncthreads();

    const uint32_t z5Hi_a = smem_to_u32(z5Hi);
    const uint32_t z5Lo_a = smem_to_u32(z5Lo);
    const uint32_t z6Hi_a = smem_to_u32(z6Hi);
    const uint32_t z6Lo_a = smem_to_u32(z6Lo);
    const uint32_t hHi_a  = smem_to_u32(hHi);
    const uint32_t hLo_a  = smem_to_u32(hLo);
    const uint32_t whi_a  = smem_to_u32(whi32);
    const uint32_t wlo_a  = whi_a + 3072 * 4;   // blocks 5/6 lo offset
    const uint32_t wlo7_a = whi_a + 2560 * 4;   // block7 lo offset
    const int m0 = (wid & 1) * 32;   // 2 M-warps
    const int wn = wid >> 1;         // 4 N-warps

    // ---- block5: z5 = relu(h @ W5a^T + c5). 2 N-passes of 256, K=64.
    for (int cc = 0; cc < 2; cc++) {
        float acc[2][8][4];
#pragma unroll
        for (int mi = 0; mi < 2; mi++)
#pragma unroll
            for (int nj = 0; nj < 8; nj++)
#pragma unroll
                for (int q = 0; q < 4; q++) acc[mi][nj][q] = 0.f;
        for (int s = 0; s < 4; s++) {
            __syncthreads();
            stsP<6>(whi32, rwp);
            int t = cc * 4 + s + 1;
            if (t < 8)       ldgP<6>(rwp, g_w5 + t * 6144);
            else if (t == 8) ldgP<6>(rwp, g_w6);
            __syncthreads();
            gemm_kstep_p<4>(hHi_a, hLo_a, 72, m0, whi_a, wlo_a, 24,
                            wn * 64, 0, s * 16, lane, acc);
        }
        epi_store_p<8>(z5Hi, z5Lo, 260, m0, cc * 256 + wn * 64, g_c5, acc, lane);
    }

    // ---- block6: z6 = relu(z5 @ W6^T + b6). N=256, K=512.
    {
        float acc[2][8][4];
#pragma unroll
        for (int mi = 0; mi < 2; mi++)
#pragma unroll
            for (int nj = 0; nj < 8; nj++)
#pragma unroll
                for (int q = 0; q < 4; q++) acc[mi][nj][q] = 0.f;
        for (int s = 0; s < 32; s++) {
            __syncthreads();
            stsP<6>(whi32, rwp);
            int t = s + 1;
            if (t < 32) ldgP<6>(rwp, g_w6 + t * 6144);
            else        ldgP<5>(rwp, g_w7);   // block7 slab 0 (5 uint4)
            __syncthreads();
            gemm_kstep_p<4>(z5Hi_a, z5Lo_a, 520, m0, whi_a, wlo_a, 24,
                            wn * 64, 0, s * 16, lane, acc);
        }
        epi_store_p<8>(z6Hi, z6Lo, 132, m0, wn * 64, b6, acc, lane);
    }

    // ---- block7: z7 = relu(z6 @ W7^T + b7). N=128, K=256. fp32 out over z5.
    {
        float acc[2][4][4];
#pragma unroll
        for (int mi = 0; mi < 2; mi++)
#pragma unroll
            for (int nj = 0; nj < 4; nj++)
#pragma unroll
                for (int q = 0; q < 4; q++) acc[mi][nj][q] = 0.f;
        for (int s = 0; s < 8; s++) {
            __syncthreads();
            stsP<5>(whi32, rwp);
            if (s < 7) ldgP<5>(rwp, g_w7 + (s + 1) * 5120);
            __syncthreads();
            gemm_kstep_p<2>(z6Hi_a, z6Lo_a, 264, m0, whi_a, wlo7_a, 40,
                            wn * 32, 0,  s * 32,      lane, acc);
            gemm_kstep_p<2>(z6Hi_a, z6Lo_a, 264, m0, whi_a, wlo7_a, 40,
                            wn * 32, 16, s * 32 + 16, lane, acc);
        }
        __syncthreads();   // z5 planes dead; safe to overlay z7 fp32
        epi_store<4>(z7, 132, m0, wn * 32, b7, acc, lane);
    }
    __syncthreads();

    // ---- block8: out = z7 @ W8^T + b8 (no relu)
    if (tid < 64) {
        const float* zr = z7 + tid * 132;
        float s = __ldg(b8);
#pragma unroll 8
        for (int k = 0; k < 128; k++) s = fmaf(zr[k], __ldg(W8 + k), s);
        out[pbase + tid] = s;
    }
}

// ============================================================
extern "C" void kernel_launch(void* const* d_in, const int* in_sizes, int n_in,
                              void* d_out, int out_size) {
    const float* x  = (const float*)d_in[0];
    const float* W1 = (const float*)d_in[1];  const float* b1 = (const float*)d_in[2];
    const float* W2 = (const float*)d_in[3];  const float* b2 = (const float*)d_in[4];
    const float* W3 = (const float*)d_in[5];  const float* b3 = (const float*)d_in[6];
    const float* W4 = (const float*)d_in[7];  const float* b4 = (const float*)d_in[8];
    const float* W5 = (const float*)d_in[9];  const float* b5 = (const float*)d_in[10];
    const float* W6 = (const float*)d_in[11]; const float* b6 = (const float*)d_in[12];
    const float* W7 = (const float*)d_in[13]; const float* b7 = (const float*)d_in[14];
    const float* W8 = (const float*)d_in[15]; const float* b8 = (const float*)d_in[16];
    float* out = (float*)d_out;

    const int n = in_sizes[0] / 3;  // 65536

    const int smem1 = SMEM1_FLOATS * (int)sizeof(float);
    const int smem3 = SMEM3_FLOATS * (int)sizeof(float);
    cudaFuncSetAttribute(k_front, cudaFuncAttributeMaxDynamicSharedMemorySize, smem1);
    cudaFuncSetAttribute(k_back,  cudaFuncAttributeMaxDynamicSharedMemorySize, smem3);

    k_init<<<1, 1024>>>();
    k_prep<<<128, 256>>>(W2, W3, W4, W5, W6, W7);
    k_front<<<n / 128, NT, smem1>>>(x, W1, b1, b2, b3, b4);
    k_c5<<<64, 256>>>(W5, b5);
    k_back<<<n / 64, NT, smem3>>>(b6, b7, W8, b8, out);
}